// round 5
// baseline (speedup 1.0000x reference)
#include <cuda_runtime.h>
#include <math.h>

// Problem dims
#define E_ 8
#define S_ 64
#define H_ 2048
#define D_ 1024
#define B_ 8192
#define LN_EPS 1e-5f

// GEMM tiling
#define TM 128
#define TN 128
#define TK 8
#define NGROUPS 16                     // (expert, sel) pairs
#define P_MAX (B_ + NGROUPS * TM)      // padded permuted length = 10240
#define MTILES (P_MAX / TM)            // 80

// Scratch (device globals — no allocation allowed)
__device__ int   g_perm[P_MAX];
__device__ int   g_tile_group[MTILES];
__device__ float g_h1[(size_t)B_ * H_];    // 64 MB
__device__ float g_mid[(size_t)B_ * D_];   // 32 MB
__device__ float g_h2[(size_t)B_ * H_];    // 64 MB

// ---------------------------------------------------------------------------
// Build row groups: group = expert*2 + has_proprio. Rows of each group are
// packed contiguously in g_perm at a TM-aligned offset; padding slots = -1.
// g_tile_group[mt] gives the group of tile mt (-1 = unused tile).
// Output values are independent of intra-group order -> deterministic result.
// ---------------------------------------------------------------------------
__global__ void build_groups(const int* __restrict__ hp, const int* __restrict__ ei)
{
    __shared__ int cnt[NGROUPS];
    __shared__ int cur[NGROUPS];
    int t = threadIdx.x;
    if (t < NGROUPS) cnt[t] = 0;
    __syncthreads();

    for (int r = t; r < B_; r += blockDim.x) {
        int g = ei[r] * 2 + (hp[r] != 0);
        atomicAdd(&cnt[g], 1);
    }
    for (int i = t; i < P_MAX; i += blockDim.x) g_perm[i] = -1;
    __syncthreads();

    if (t == 0) {
        int off = 0;
        for (int g = 0; g < NGROUPS; g++) {
            cur[g] = off;
            int ntile = (cnt[g] + TM - 1) / TM;
            int t0 = off / TM;
            for (int k = 0; k < ntile; k++) g_tile_group[t0 + k] = g;
            off += ntile * TM;
        }
        for (int k = off / TM; k < MTILES; k++) g_tile_group[k] = -1;
    }
    __syncthreads();

    for (int r = t; r < B_; r += blockDim.x) {
        int g = ei[r] * 2 + (hp[r] != 0);
        int pos = atomicAdd(&cur[g], 1);
        g_perm[pos] = r;
    }
}

// ---------------------------------------------------------------------------
// Grouped SGEMM: Out[row, n] = act( A[row, :] @ W[e][:, n] + bias[e][n] )
// W selected per-group from (Wp, Wq) by sel bit. 128x128x8 tile, 256 threads,
// 8x8 microtile per thread. Rows gathered through g_perm.
// ---------------------------------------------------------------------------
template<bool GELU>
__global__ __launch_bounds__(256)
void gemm_grouped(const float* __restrict__ A, int K, int N,
                  const float* __restrict__ Wp, const float* __restrict__ Wq,
                  const float* __restrict__ bp, const float* __restrict__ bq,
                  float* __restrict__ Out)
{
    int mt = blockIdx.y;
    int g = g_tile_group[mt];
    if (g < 0) return;
    int e = g >> 1, sel = g & 1;
    const float* W    = (sel ? Wq : Wp) + (size_t)e * K * N;
    const float* bias = (sel ? bq : bp) + (size_t)e * N;
    int n0 = blockIdx.x * TN;

    __shared__ float As[TK][TM];
    __shared__ float Bs[TK][TN];
    __shared__ int   rows_s[TM];

    int t = threadIdx.x;               // 0..255
    if (t < TM) rows_s[t] = g_perm[mt * TM + t];
    __syncthreads();

    int tx = t & 15, ty = t >> 4;      // 16 x 16 thread grid

    // A load mapping: thread -> (row ia, 4 consecutive k)
    int ia = t >> 1;
    int ka = (t & 1) * 4;
    int rowA = rows_s[ia];
    const float* Aptr = (rowA >= 0) ? (A + (size_t)rowA * K + ka) : A;

    // B load mapping: thread -> (k row kb, 4 consecutive n)
    int kb = t >> 5;
    int jb = (t & 31) * 4;

    float acc[8][8];
    #pragma unroll
    for (int i = 0; i < 8; i++)
        #pragma unroll
        for (int j = 0; j < 8; j++) acc[i][j] = 0.0f;

    for (int k0 = 0; k0 < K; k0 += TK) {
        float4 av = make_float4(0.f, 0.f, 0.f, 0.f);
        if (rowA >= 0) av = *(const float4*)(Aptr + k0);
        As[ka + 0][ia] = av.x;
        As[ka + 1][ia] = av.y;
        As[ka + 2][ia] = av.z;
        As[ka + 3][ia] = av.w;

        float4 bv = *(const float4*)(W + (size_t)(k0 + kb) * N + n0 + jb);
        *(float4*)&Bs[kb][jb] = bv;
        __syncthreads();

        #pragma unroll
        for (int kk = 0; kk < TK; kk++) {
            float4 a0 = *(const float4*)&As[kk][ty * 8];
            float4 a1 = *(const float4*)&As[kk][ty * 8 + 4];
            float4 b0 = *(const float4*)&Bs[kk][tx * 8];
            float4 b1 = *(const float4*)&Bs[kk][tx * 8 + 4];
            float a[8] = {a0.x, a0.y, a0.z, a0.w, a1.x, a1.y, a1.z, a1.w};
            float b[8] = {b0.x, b0.y, b0.z, b0.w, b1.x, b1.y, b1.z, b1.w};
            #pragma unroll
            for (int i = 0; i < 8; i++)
                #pragma unroll
                for (int j = 0; j < 8; j++) acc[i][j] += a[i] * b[j];
        }
        __syncthreads();
    }

    // Epilogue: bias (+ exact-erf GELU), scatter to original row indices.
    #pragma unroll
    for (int i = 0; i < 8; i++) {
        int r = rows_s[ty * 8 + i];
        if (r < 0) continue;
        float* outp = Out + (size_t)r * N + n0 + tx * 8;
        #pragma unroll
        for (int j = 0; j < 8; j++) {
            float v = acc[i][j] + bias[n0 + tx * 8 + j];
            if (GELU) v = 0.5f * v * (1.0f + erff(v * 0.7071067811865475f));
            outp[j] = v;
        }
    }
}

// ---------------------------------------------------------------------------
// LayerNorm over D=1024, per original row, in place on g_mid.
// ---------------------------------------------------------------------------
__global__ __launch_bounds__(256)
void layernorm_k(const int* __restrict__ ei,
                 const float* __restrict__ ln_g, const float* __restrict__ ln_b,
                 float* __restrict__ mid)
{
    int r = blockIdx.x;
    int e = ei[r];
    float* x = mid + (size_t)r * D_;
    int t = threadIdx.x;

    float v[4];
    float s = 0.f, ss = 0.f;
    #pragma unroll
    for (int i = 0; i < 4; i++) {
        v[i] = x[t + i * 256];
        s += v[i];
        ss += v[i] * v[i];
    }
    #pragma unroll
    for (int o = 16; o; o >>= 1) {
        s  += __shfl_xor_sync(0xffffffffu, s,  o);
        ss += __shfl_xor_sync(0xffffffffu, ss, o);
    }
    __shared__ float red[2][8];
    int w = t >> 5, l = t & 31;
    if (l == 0) { red[0][w] = s; red[1][w] = ss; }
    __syncthreads();
    float S = 0.f, SS = 0.f;
    #pragma unroll
    for (int i = 0; i < 8; i++) { S += red[0][i]; SS += red[1][i]; }

    float mu  = S * (1.0f / D_);
    float var = SS * (1.0f / D_) - mu * mu;
    float rstd = rsqrtf(var + LN_EPS);

    const float* gg = ln_g + (size_t)e * D_;
    const float* bb = ln_b + (size_t)e * D_;
    #pragma unroll
    for (int i = 0; i < 4; i++) {
        int c = t + i * 256;
        x[c] = (v[i] - mu) * rstd * gg[c] + bb[c];
    }
}

// ---------------------------------------------------------------------------
extern "C" void kernel_launch(void* const* d_in, const int* in_sizes, int n_in,
                              void* d_out, int out_size)
{
    const float* x   = (const float*)d_in[0];
    const int*   hp  = (const int*)d_in[1];
    const int*   ei  = (const int*)d_in[2];
    const float* pw1 = (const float*)d_in[3];
    const float* pb1 = (const float*)d_in[4];
    const float* pw2 = (const float*)d_in[5];
    const float* pb2 = (const float*)d_in[6];
    const float* qw1 = (const float*)d_in[7];
    const float* qb1 = (const float*)d_in[8];
    const float* qw2 = (const float*)d_in[9];
    const float* qb2 = (const float*)d_in[10];
    const float* lng = (const float*)d_in[11];
    const float* lnb = (const float*)d_in[12];
    const float* tw1 = (const float*)d_in[13];
    const float* tb1 = (const float*)d_in[14];
    const float* tw2 = (const float*)d_in[15];
    const float* tb2 = (const float*)d_in[16];
    float* out = (float*)d_out;

    float *h1, *mid, *h2;
    cudaGetSymbolAddress((void**)&h1,  g_h1);
    cudaGetSymbolAddress((void**)&mid, g_mid);
    cudaGetSymbolAddress((void**)&h2,  g_h2);

    build_groups<<<1, 256>>>(hp, ei);

    // Stage 1: h1 = gelu(x @ {p,q}w1 + {p,q}b1)        [rows,64]@[64,2048]
    gemm_grouped<true ><<<dim3(H_ / TN, MTILES), 256>>>(x,   S_, H_, pw1, qw1, pb1, qb1, h1);
    // Stage 2: mid = h1 @ {p,q}w2 + {p,q}b2            [rows,2048]@[2048,1024]
    gemm_grouped<false><<<dim3(D_ / TN, MTILES), 256>>>(h1,  H_, D_, pw2, qw2, pb2, qb2, mid);
    // Stage 3: layernorm (in place on mid)
    layernorm_k<<<B_, 256>>>(ei, lng, lnb, mid);
    // Stage 4: h2 = gelu(mid @ tw1 + tb1)              [rows,1024]@[1024,2048]
    gemm_grouped<true ><<<dim3(H_ / TN, MTILES), 256>>>(mid, D_, H_, tw1, tw1, tb1, tb1, h2);
    // Stage 5: out = h2 @ tw2 + tb2                    [rows,2048]@[2048,1024]
    gemm_grouped<false><<<dim3(D_ / TN, MTILES), 256>>>(h2,  H_, D_, tw2, tw2, tb2, tb2, out);
}

// round 7
// speedup vs baseline: 2.4728x; 2.4728x over previous
#include <cuda_runtime.h>
#include <cuda_bf16.h>
#include <math.h>
#include <stdint.h>
#include <cstdint>
#include <cstddef>

// Problem dims
#define E_ 8
#define S_ 64
#define H_ 2048
#define D_ 1024
#define B_ 8192
#define LN_EPS 1e-5f

// GEMM tiling
#define TM 128
#define TN 128
#define TKK 32                          // K per mainloop iteration
#define NGROUPS 16                      // (expert, sel) pairs
#define P_MAX (B_ + NGROUPS * TM)       // padded permuted length = 10240
#define MTILES (P_MAX / TM)             // 80

#define LDA_S 40                        // As row stride in bf16 (32 + 8 pad)
#define LDB_S 136                       // Bs row stride in bf16 (128 + 8 pad)

// Scratch (device globals — no allocation allowed)
__device__ int   g_perm[P_MAX];
__device__ int   g_tile_group[MTILES];
__device__ float g_h1[(size_t)B_ * H_];
__device__ float g_mid[(size_t)B_ * D_];
__device__ float g_h2[(size_t)B_ * H_];

// ---------------------------------------------------------------------------
// Group builder: group = expert*2 + has_proprio; rows packed contiguously at
// TM-aligned offsets; padding slots = -1.
// ---------------------------------------------------------------------------
__global__ void build_groups(const int* __restrict__ hp, const int* __restrict__ ei)
{
    __shared__ int cnt[NGROUPS];
    __shared__ int cur[NGROUPS];
    int t = threadIdx.x;
    if (t < NGROUPS) cnt[t] = 0;
    __syncthreads();

    for (int r = t; r < B_; r += blockDim.x) {
        int g = ei[r] * 2 + (hp[r] != 0);
        atomicAdd(&cnt[g], 1);
    }
    for (int i = t; i < P_MAX; i += blockDim.x) g_perm[i] = -1;
    __syncthreads();

    if (t == 0) {
        int off = 0;
        for (int g = 0; g < NGROUPS; g++) {
            cur[g] = off;
            int ntile = (cnt[g] + TM - 1) / TM;
            int t0 = off / TM;
            for (int k = 0; k < ntile; k++) g_tile_group[t0 + k] = g;
            off += ntile * TM;
        }
        for (int k = off / TM; k < MTILES; k++) g_tile_group[k] = -1;
    }
    __syncthreads();

    for (int r = t; r < B_; r += blockDim.x) {
        int g = ei[r] * 2 + (hp[r] != 0);
        int pos = atomicAdd(&cur[g], 1);
        g_perm[pos] = r;
    }
}

// ---------------------------------------------------------------------------
// PTX helpers
// ---------------------------------------------------------------------------
__device__ __forceinline__ void ldsm_x4(uint32_t* r, uint32_t addr) {
    asm volatile("ldmatrix.sync.aligned.m8n8.x4.shared.b16 {%0,%1,%2,%3}, [%4];\n"
                 : "=r"(r[0]), "=r"(r[1]), "=r"(r[2]), "=r"(r[3]) : "r"(addr));
}
__device__ __forceinline__ void ldsm_x4_t(uint32_t* r, uint32_t addr) {
    asm volatile("ldmatrix.sync.aligned.m8n8.x4.trans.shared.b16 {%0,%1,%2,%3}, [%4];\n"
                 : "=r"(r[0]), "=r"(r[1]), "=r"(r[2]), "=r"(r[3]) : "r"(addr));
}
__device__ __forceinline__ void mma_bf16(float* c, const uint32_t* a,
                                         uint32_t b0, uint32_t b1) {
    asm volatile("mma.sync.aligned.m16n8k16.row.col.f32.bf16.bf16.f32 "
                 "{%0,%1,%2,%3}, {%4,%5,%6,%7}, {%8,%9}, {%0,%1,%2,%3};\n"
                 : "+f"(c[0]), "+f"(c[1]), "+f"(c[2]), "+f"(c[3])
                 : "r"(a[0]), "r"(a[1]), "r"(a[2]), "r"(a[3]), "r"(b0), "r"(b1));
}
__device__ __forceinline__ void split_bf16(float a, __nv_bfloat16& hi, __nv_bfloat16& lo) {
    hi = __float2bfloat16(a);
    lo = __float2bfloat16(a - __bfloat162float(hi));
}

// ---------------------------------------------------------------------------
// Grouped GEMM, split-bf16 tensor-core path (3 HMMA products: hh + lh + hl).
// Block tile 128x128xTKK, 256 threads = 8 warps, warp tile 32x64.
// ---------------------------------------------------------------------------
template<bool GELU>
__global__ __launch_bounds__(256, 2)
void gemm_tc(const float* __restrict__ A, int K, int N,
             const float* __restrict__ Wp, const float* __restrict__ Wq,
             const float* __restrict__ bp, const float* __restrict__ bq,
             float* __restrict__ Out)
{
    int mt = blockIdx.y;
    int g = g_tile_group[mt];
    if (g < 0) return;
    int e = g >> 1, sel = g & 1;
    const float* W    = (sel ? Wq : Wp) + (size_t)e * K * N;
    const float* bias = (sel ? bq : bp) + (size_t)e * N;
    int n0 = blockIdx.x * TN;

    __shared__ __align__(16) __nv_bfloat16 As_hi[TM * LDA_S];
    __shared__ __align__(16) __nv_bfloat16 As_lo[TM * LDA_S];
    __shared__ __align__(16) __nv_bfloat16 Bs_hi[TKK * LDB_S];
    __shared__ __align__(16) __nv_bfloat16 Bs_lo[TKK * LDB_S];
    __shared__ int rows_s[TM];

    int t = threadIdx.x;
    if (t < TM) rows_s[t] = g_perm[mt * TM + t];
    __syncthreads();

    int lane = t & 31;
    int wid  = t >> 5;
    int wr = wid & 3;          // M:  4 warps * 32
    int wc = wid >> 2;         // N:  2 warps * 64

    uint32_t as_hi_u = (uint32_t)__cvta_generic_to_shared(As_hi);
    uint32_t as_lo_u = (uint32_t)__cvta_generic_to_shared(As_lo);
    uint32_t bs_hi_u = (uint32_t)__cvta_generic_to_shared(Bs_hi);
    uint32_t bs_lo_u = (uint32_t)__cvta_generic_to_shared(Bs_lo);

    // Loader mappings
    int ia_row = t >> 1;                    // 0..127
    int ia_col = (t & 1) << 4;              // 0 or 16
    int rowA = rows_s[ia_row];
    const float* Ap = (rowA >= 0) ? A + (size_t)rowA * K + ia_col : (const float*)0;

    int ib_k = t >> 3;                      // 0..31
    int ib_n = (t & 7) << 4;                // 0..112
    const float* Bp = W + (size_t)ib_k * N + n0 + ib_n;

    // ldmatrix address components
    int a_row_off = lane & 15;
    int a_col_off = (lane >> 4) << 3;       // 0 or 8
    int bm = lane >> 3;
    int b_krow_off = ((bm & 1) << 3) + (lane & 7);
    int b_ncol_off = (bm >> 1) << 3;

    float acc[2][8][4];
    #pragma unroll
    for (int mi = 0; mi < 2; mi++)
        #pragma unroll
        for (int ni = 0; ni < 8; ni++)
            #pragma unroll
            for (int q = 0; q < 4; q++) acc[mi][ni][q] = 0.0f;

    for (int k0 = 0; k0 < K; k0 += TKK) {
        // ---- gmem loads (issued before the barrier to overlap drain) ----
        float va[16], vb[16];
        #pragma unroll
        for (int i = 0; i < 4; i++) {
            float4 v = Ap ? *(const float4*)(Ap + k0 + i * 4)
                          : make_float4(0.f, 0.f, 0.f, 0.f);
            va[i*4+0] = v.x; va[i*4+1] = v.y; va[i*4+2] = v.z; va[i*4+3] = v.w;
        }
        #pragma unroll
        for (int i = 0; i < 4; i++) {
            float4 v = *(const float4*)(Bp + (size_t)k0 * N + i * 4);
            vb[i*4+0] = v.x; vb[i*4+1] = v.y; vb[i*4+2] = v.z; vb[i*4+3] = v.w;
        }

        __syncthreads();   // previous tile fully consumed

        // ---- convert + store to smem ----
        {
            __nv_bfloat16 h[16], l[16];
            #pragma unroll
            for (int i = 0; i < 16; i++) split_bf16(va[i], h[i], l[i]);
            uint4* dh = (uint4*)&As_hi[ia_row * LDA_S + ia_col];
            uint4* dl = (uint4*)&As_lo[ia_row * LDA_S + ia_col];
            dh[0] = *(uint4*)&h[0]; dh[1] = *(uint4*)&h[8];
            dl[0] = *(uint4*)&l[0]; dl[1] = *(uint4*)&l[8];
            #pragma unroll
            for (int i = 0; i < 16; i++) split_bf16(vb[i], h[i], l[i]);
            uint4* eh = (uint4*)&Bs_hi[ib_k * LDB_S + ib_n];
            uint4* el = (uint4*)&Bs_lo[ib_k * LDB_S + ib_n];
            eh[0] = *(uint4*)&h[0]; eh[1] = *(uint4*)&h[8];
            el[0] = *(uint4*)&l[0]; el[1] = *(uint4*)&l[8];
        }
        __syncthreads();

        // ---- tensor-core compute: (ah*bh + al*bh) then (ah*bl) ----
        #pragma unroll
        for (int ks = 0; ks < 2; ks++) {
            uint32_t a_hi[2][4], a_lo[2][4], bfr[4];
            #pragma unroll
            for (int mi = 0; mi < 2; mi++) {
                int row = wr * 32 + mi * 16 + a_row_off;
                int cb  = ks * 16 + a_col_off;
                uint32_t off = (uint32_t)(row * LDA_S + cb) * 2u;
                ldsm_x4(a_hi[mi], as_hi_u + off);
                ldsm_x4(a_lo[mi], as_lo_u + off);
            }
            int krow = ks * 16 + b_krow_off;
            #pragma unroll
            for (int j = 0; j < 4; j++) {
                int ncol = wc * 64 + j * 16 + b_ncol_off;
                uint32_t off = (uint32_t)(krow * LDB_S + ncol) * 2u;
                ldsm_x4_t(bfr, bs_hi_u + off);
                #pragma unroll
                for (int mi = 0; mi < 2; mi++) {
                    mma_bf16(acc[mi][2*j+0], a_hi[mi], bfr[0], bfr[1]);
                    mma_bf16(acc[mi][2*j+1], a_hi[mi], bfr[2], bfr[3]);
                    mma_bf16(acc[mi][2*j+0], a_lo[mi], bfr[0], bfr[1]);
                    mma_bf16(acc[mi][2*j+1], a_lo[mi], bfr[2], bfr[3]);
                }
            }
            #pragma unroll
            for (int j = 0; j < 4; j++) {
                int ncol = wc * 64 + j * 16 + b_ncol_off;
                uint32_t off = (uint32_t)(krow * LDB_S + ncol) * 2u;
                ldsm_x4_t(bfr, bs_lo_u + off);
                #pragma unroll
                for (int mi = 0; mi < 2; mi++) {
                    mma_bf16(acc[mi][2*j+0], a_hi[mi], bfr[0], bfr[1]);
                    mma_bf16(acc[mi][2*j+1], a_hi[mi], bfr[2], bfr[3]);
                }
            }
        }
    }

    // ---- epilogue: bias (+ exact-erf GELU), scatter to original rows ----
    #pragma unroll
    for (int mi = 0; mi < 2; mi++) {
        #pragma unroll
        for (int half = 0; half < 2; half++) {
            int mrow = wr * 32 + mi * 16 + half * 8 + (lane >> 2);
            int r = rows_s[mrow];
            if (r < 0) continue;
            float* outp = Out + (size_t)r * N;
            #pragma unroll
            for (int ni = 0; ni < 8; ni++) {
                int col = n0 + wc * 64 + ni * 8 + ((lane & 3) << 1);
                float v0 = acc[mi][ni][half * 2 + 0] + bias[col];
                float v1 = acc[mi][ni][half * 2 + 1] + bias[col + 1];
                if (GELU) {
                    v0 = 0.5f * v0 * (1.0f + erff(v0 * 0.7071067811865475f));
                    v1 = 0.5f * v1 * (1.0f + erff(v1 * 0.7071067811865475f));
                }
                *(float2*)(outp + col) = make_float2(v0, v1);
            }
        }
    }
}

// ---------------------------------------------------------------------------
// LayerNorm over D=1024 (unchanged)
// ---------------------------------------------------------------------------
__global__ __launch_bounds__(256)
void layernorm_k(const int* __restrict__ ei,
                 const float* __restrict__ ln_g, const float* __restrict__ ln_b,
                 float* __restrict__ mid)
{
    int r = blockIdx.x;
    int e = ei[r];
    float* x = mid + (size_t)r * D_;
    int t = threadIdx.x;

    float v[4];
    float s = 0.f, ss = 0.f;
    #pragma unroll
    for (int i = 0; i < 4; i++) {
        v[i] = x[t + i * 256];
        s += v[i];
        ss += v[i] * v[i];
    }
    #pragma unroll
    for (int o = 16; o; o >>= 1) {
        s  += __shfl_xor_sync(0xffffffffu, s,  o);
        ss += __shfl_xor_sync(0xffffffffu, ss, o);
    }
    __shared__ float red[2][8];
    int w = t >> 5, l = t & 31;
    if (l == 0) { red[0][w] = s; red[1][w] = ss; }
    __syncthreads();
    float S = 0.f, SS = 0.f;
    #pragma unroll
    for (int i = 0; i < 8; i++) { S += red[0][i]; SS += red[1][i]; }

    float mu  = S * (1.0f / D_);
    float var = SS * (1.0f / D_) - mu * mu;
    float rstd = rsqrtf(var + LN_EPS);

    const float* gg = ln_g + (size_t)e * D_;
    const float* bb = ln_b + (size_t)e * D_;
    #pragma unroll
    for (int i = 0; i < 4; i++) {
        int c = t + i * 256;
        x[c] = (v[i] - mu) * rstd * gg[c] + bb[c];
    }
}

// ---------------------------------------------------------------------------
extern "C" void kernel_launch(void* const* d_in, const int* in_sizes, int n_in,
                              void* d_out, int out_size)
{
    const float* x   = (const float*)d_in[0];
    const int*   hp  = (const int*)d_in[1];
    const int*   ei  = (const int*)d_in[2];
    const float* pw1 = (const float*)d_in[3];
    const float* pb1 = (const float*)d_in[4];
    const float* pw2 = (const float*)d_in[5];
    const float* pb2 = (const float*)d_in[6];
    const float* qw1 = (const float*)d_in[7];
    const float* qb1 = (const float*)d_in[8];
    const float* qw2 = (const float*)d_in[9];
    const float* qb2 = (const float*)d_in[10];
    const float* lng = (const float*)d_in[11];
    const float* lnb = (const float*)d_in[12];
    const float* tw1 = (const float*)d_in[13];
    const float* tb1 = (const float*)d_in[14];
    const float* tw2 = (const float*)d_in[15];
    const float* tb2 = (const float*)d_in[16];
    float* out = (float*)d_out;

    float *h1, *mid, *h2;
    cudaGetSymbolAddress((void**)&h1,  g_h1);
    cudaGetSymbolAddress((void**)&mid, g_mid);
    cudaGetSymbolAddress((void**)&h2,  g_h2);

    build_groups<<<1, 256>>>(hp, ei);

    // Stage 1: h1 = gelu(x @ {p,q}w1 + b1)     K=64
    gemm_tc<true ><<<dim3(H_ / TN, MTILES), 256>>>(x,   S_, H_, pw1, qw1, pb1, qb1, h1);
    // Stage 2: mid = h1 @ {p,q}w2 + b2         K=2048
    gemm_tc<false><<<dim3(D_ / TN, MTILES), 256>>>(h1,  H_, D_, pw2, qw2, pb2, qb2, mid);
    // Stage 3: layernorm in place
    layernorm_k<<<B_, 256>>>(ei, lng, lnb, mid);
    // Stage 4: h2 = gelu(mid @ tw1 + tb1)      K=1024
    gemm_tc<true ><<<dim3(H_ / TN, MTILES), 256>>>(mid, D_, H_, tw1, tw1, tb1, tb1, h2);
    // Stage 5: out = h2 @ tw2 + tb2            K=2048
    gemm_tc<false><<<dim3(D_ / TN, MTILES), 256>>>(h2,  H_, D_, tw2, tw2, tb2, tb2, out);
}

// round 8
// speedup vs baseline: 2.6707x; 1.0800x over previous
#include <cuda_runtime.h>
#include <cuda_bf16.h>
#include <math.h>
#include <stdint.h>
#include <cstdint>
#include <cstddef>

// Problem dims
#define E_ 8
#define S_ 64
#define H_ 2048
#define D_ 1024
#define B_ 8192
#define LN_EPS 1e-5f

// GEMM tiling
#define TM 128
#define TN 128
#define TKK 32                          // K per mainloop iteration
#define NGROUPS 16                      // (expert, sel) pairs
#define P_MAX (B_ + NGROUPS * TM)       // padded permuted length = 10240
#define MTILES (P_MAX / TM)             // 80

#define LDA_S 40                        // As row stride in bf16 (32 + 8 pad)
#define LDB_S 136                       // Bs row stride in bf16 (128 + 8 pad)

// Dynamic smem layout (elements)
#define A_PL (TM * LDA_S)               // 5120 bf16 per A plane per buffer
#define B_PL (TKK * LDB_S)              // 4352 bf16 per B plane per buffer
// bytes: [As_hi:2 bufs][As_lo:2][Bs_hi:2][Bs_lo:2][rows:128 int]
#define OFF_AS_HI 0
#define OFF_AS_LO (OFF_AS_HI + 2 * A_PL)
#define OFF_BS_HI (OFF_AS_LO + 2 * A_PL)
#define OFF_BS_LO (OFF_BS_HI + 2 * B_PL)
#define SMEM_BF16_TOT (OFF_BS_LO + 2 * B_PL)          // in bf16 elements
#define SMEM_BYTES (SMEM_BF16_TOT * 2 + TM * 4)       // + rows_s ints

// Scratch (device globals — no allocation allowed)
__device__ int   g_perm[P_MAX];
__device__ int   g_tile_group[MTILES];
__device__ float g_h1[(size_t)B_ * H_];
__device__ float g_mid[(size_t)B_ * D_];
__device__ float g_h2[(size_t)B_ * H_];

// ---------------------------------------------------------------------------
// Group builder: group = expert*2 + has_proprio; rows packed contiguously at
// TM-aligned offsets; padding slots = -1.
// ---------------------------------------------------------------------------
__global__ void build_groups(const int* __restrict__ hp, const int* __restrict__ ei)
{
    __shared__ int cnt[NGROUPS];
    __shared__ int cur[NGROUPS];
    int t = threadIdx.x;
    if (t < NGROUPS) cnt[t] = 0;
    __syncthreads();

    for (int r = t; r < B_; r += blockDim.x) {
        int g = ei[r] * 2 + (hp[r] != 0);
        atomicAdd(&cnt[g], 1);
    }
    for (int i = t; i < P_MAX; i += blockDim.x) g_perm[i] = -1;
    __syncthreads();

    if (t == 0) {
        int off = 0;
        for (int g = 0; g < NGROUPS; g++) {
            cur[g] = off;
            int ntile = (cnt[g] + TM - 1) / TM;
            int t0 = off / TM;
            for (int k = 0; k < ntile; k++) g_tile_group[t0 + k] = g;
            off += ntile * TM;
        }
        for (int k = off / TM; k < MTILES; k++) g_tile_group[k] = -1;
    }
    __syncthreads();

    for (int r = t; r < B_; r += blockDim.x) {
        int g = ei[r] * 2 + (hp[r] != 0);
        int pos = atomicAdd(&cur[g], 1);
        g_perm[pos] = r;
    }
}

// ---------------------------------------------------------------------------
// PTX helpers
// ---------------------------------------------------------------------------
__device__ __forceinline__ void ldsm_x4(uint32_t* r, uint32_t addr) {
    asm volatile("ldmatrix.sync.aligned.m8n8.x4.shared.b16 {%0,%1,%2,%3}, [%4];\n"
                 : "=r"(r[0]), "=r"(r[1]), "=r"(r[2]), "=r"(r[3]) : "r"(addr));
}
__device__ __forceinline__ void ldsm_x4_t(uint32_t* r, uint32_t addr) {
    asm volatile("ldmatrix.sync.aligned.m8n8.x4.trans.shared.b16 {%0,%1,%2,%3}, [%4];\n"
                 : "=r"(r[0]), "=r"(r[1]), "=r"(r[2]), "=r"(r[3]) : "r"(addr));
}
__device__ __forceinline__ void mma_bf16(float* c, const uint32_t* a,
                                         uint32_t b0, uint32_t b1) {
    asm volatile("mma.sync.aligned.m16n8k16.row.col.f32.bf16.bf16.f32 "
                 "{%0,%1,%2,%3}, {%4,%5,%6,%7}, {%8,%9}, {%0,%1,%2,%3};\n"
                 : "+f"(c[0]), "+f"(c[1]), "+f"(c[2]), "+f"(c[3])
                 : "r"(a[0]), "r"(a[1]), "r"(a[2]), "r"(a[3]), "r"(b0), "r"(b1));
}
__device__ __forceinline__ void split_bf16(float a, __nv_bfloat16& hi, __nv_bfloat16& lo) {
    hi = __float2bfloat16(a);
    lo = __float2bfloat16(a - __bfloat162float(hi));
}

// ---------------------------------------------------------------------------
// Grouped GEMM, split-bf16 tensor-core path (hh + lh + hl), ping-pong
// double-buffered smem, one __syncthreads per K-tile.
// Block tile 128x128xTKK, 256 threads = 8 warps, warp tile 32x64.
// ---------------------------------------------------------------------------
template<bool GELU>
__global__ __launch_bounds__(256, 2)
void gemm_tc(const float* __restrict__ A, int K, int N,
             const float* __restrict__ Wp, const float* __restrict__ Wq,
             const float* __restrict__ bp, const float* __restrict__ bq,
             float* __restrict__ Out)
{
    int mt = blockIdx.y;
    int g = g_tile_group[mt];
    if (g < 0) return;
    int e = g >> 1, sel = g & 1;
    const float* W    = (sel ? Wq : Wp) + (size_t)e * K * N;
    const float* bias = (sel ? bq : bp) + (size_t)e * N;
    int n0 = blockIdx.x * TN;

    extern __shared__ __align__(16) __nv_bfloat16 dsm[];
    __nv_bfloat16* As_hi = dsm + OFF_AS_HI;
    __nv_bfloat16* As_lo = dsm + OFF_AS_LO;
    __nv_bfloat16* Bs_hi = dsm + OFF_BS_HI;
    __nv_bfloat16* Bs_lo = dsm + OFF_BS_LO;
    int* rows_s = (int*)(dsm + SMEM_BF16_TOT);

    int t = threadIdx.x;
    if (t < TM) rows_s[t] = g_perm[mt * TM + t];
    __syncthreads();

    int lane = t & 31;
    int wid  = t >> 5;
    int wr = wid & 3;          // M:  4 warps * 32
    int wc = wid >> 2;         // N:  2 warps * 64

    uint32_t as_hi_u = (uint32_t)__cvta_generic_to_shared(As_hi);
    uint32_t as_lo_u = (uint32_t)__cvta_generic_to_shared(As_lo);
    uint32_t bs_hi_u = (uint32_t)__cvta_generic_to_shared(Bs_hi);
    uint32_t bs_lo_u = (uint32_t)__cvta_generic_to_shared(Bs_lo);

    // Loader mappings
    int ia_row = t >> 1;                    // 0..127
    int ia_col = (t & 1) << 4;              // 0 or 16
    int rowA = rows_s[ia_row];
    const float* Ap = (rowA >= 0) ? A + (size_t)rowA * K + ia_col : (const float*)0;

    int ib_k = t >> 3;                      // 0..31
    int ib_n = (t & 7) << 4;                // 0..112
    const float* Bp = W + (size_t)ib_k * N + n0 + ib_n;

    // ldmatrix address components
    int a_row_off = lane & 15;
    int a_col_off = (lane >> 4) << 3;       // 0 or 8
    int bm = lane >> 3;
    int b_krow_off = ((bm & 1) << 3) + (lane & 7);
    int b_ncol_off = (bm >> 1) << 3;

    float acc[2][8][4];
    #pragma unroll
    for (int mi = 0; mi < 2; mi++)
        #pragma unroll
        for (int ni = 0; ni < 8; ni++)
            #pragma unroll
            for (int q = 0; q < 4; q++) acc[mi][ni][q] = 0.0f;

    // ---- helpers as lambdas ----
    auto load_tile = [&](int k0, float* va, float* vb) {
        #pragma unroll
        for (int i = 0; i < 4; i++) {
            float4 v = Ap ? *(const float4*)(Ap + k0 + i * 4)
                          : make_float4(0.f, 0.f, 0.f, 0.f);
            va[i*4+0] = v.x; va[i*4+1] = v.y; va[i*4+2] = v.z; va[i*4+3] = v.w;
        }
        #pragma unroll
        for (int i = 0; i < 4; i++) {
            float4 v = *(const float4*)(Bp + (size_t)k0 * N + i * 4);
            vb[i*4+0] = v.x; vb[i*4+1] = v.y; vb[i*4+2] = v.z; vb[i*4+3] = v.w;
        }
    };
    auto store_tile = [&](int buf, const float* va, const float* vb) {
        __nv_bfloat16 h[16], l[16];
        #pragma unroll
        for (int i = 0; i < 16; i++) split_bf16(va[i], h[i], l[i]);
        uint4* dh = (uint4*)&As_hi[buf * A_PL + ia_row * LDA_S + ia_col];
        uint4* dl = (uint4*)&As_lo[buf * A_PL + ia_row * LDA_S + ia_col];
        dh[0] = *(uint4*)&h[0]; dh[1] = *(uint4*)&h[8];
        dl[0] = *(uint4*)&l[0]; dl[1] = *(uint4*)&l[8];
        #pragma unroll
        for (int i = 0; i < 16; i++) split_bf16(vb[i], h[i], l[i]);
        uint4* eh = (uint4*)&Bs_hi[buf * B_PL + ib_k * LDB_S + ib_n];
        uint4* el = (uint4*)&Bs_lo[buf * B_PL + ib_k * LDB_S + ib_n];
        eh[0] = *(uint4*)&h[0]; eh[1] = *(uint4*)&h[8];
        el[0] = *(uint4*)&l[0]; el[1] = *(uint4*)&l[8];
    };

    // ---- prologue: fill buffer 0 ----
    float va[16], vb[16];
    load_tile(0, va, vb);
    store_tile(0, va, vb);
    __syncthreads();

    int nk = K / TKK;
    for (int it = 0; it < nk; it++) {
        int buf = it & 1;
        bool has_next = (it + 1) < nk;

        // issue next tile's gmem loads early (latency hidden by MMAs below)
        if (has_next) load_tile((it + 1) * TKK, va, vb);

        uint32_t aBaseHi = as_hi_u + (uint32_t)(buf * A_PL) * 2u;
        uint32_t aBaseLo = as_lo_u + (uint32_t)(buf * A_PL) * 2u;
        uint32_t bBaseHi = bs_hi_u + (uint32_t)(buf * B_PL) * 2u;
        uint32_t bBaseLo = bs_lo_u + (uint32_t)(buf * B_PL) * 2u;

        #pragma unroll
        for (int ks = 0; ks < 2; ks++) {
            uint32_t a_hi[2][4], a_lo[2][4], bfr[4];
            #pragma unroll
            for (int mi = 0; mi < 2; mi++) {
                int row = wr * 32 + mi * 16 + a_row_off;
                int cb  = ks * 16 + a_col_off;
                uint32_t off = (uint32_t)(row * LDA_S + cb) * 2u;
                ldsm_x4(a_hi[mi], aBaseHi + off);
                ldsm_x4(a_lo[mi], aBaseLo + off);
            }
            int krow = ks * 16 + b_krow_off;
            #pragma unroll
            for (int j = 0; j < 4; j++) {
                int ncol = wc * 64 + j * 16 + b_ncol_off;
                uint32_t off = (uint32_t)(krow * LDB_S + ncol) * 2u;
                ldsm_x4_t(bfr, bBaseHi + off);
                #pragma unroll
                for (int mi = 0; mi < 2; mi++) {
                    mma_bf16(acc[mi][2*j+0], a_hi[mi], bfr[0], bfr[1]);
                    mma_bf16(acc[mi][2*j+1], a_hi[mi], bfr[2], bfr[3]);
                    mma_bf16(acc[mi][2*j+0], a_lo[mi], bfr[0], bfr[1]);
                    mma_bf16(acc[mi][2*j+1], a_lo[mi], bfr[2], bfr[3]);
                }
            }
            #pragma unroll
            for (int j = 0; j < 4; j++) {
                int ncol = wc * 64 + j * 16 + b_ncol_off;
                uint32_t off = (uint32_t)(krow * LDB_S + ncol) * 2u;
                ldsm_x4_t(bfr, bBaseLo + off);
                #pragma unroll
                for (int mi = 0; mi < 2; mi++) {
                    mma_bf16(acc[mi][2*j+0], a_hi[mi], bfr[0], bfr[1]);
                    mma_bf16(acc[mi][2*j+1], a_hi[mi], bfr[2], bfr[3]);
                }
            }
        }

        // convert + store next tile into the other buffer (no barrier needed
        // before: different buffer than the one just computed on)
        if (has_next) store_tile(buf ^ 1, va, vb);
        __syncthreads();
    }

    // ---- epilogue: bias (+ exact-erf GELU), scatter to original rows ----
    #pragma unroll
    for (int mi = 0; mi < 2; mi++) {
        #pragma unroll
        for (int half = 0; half < 2; half++) {
            int mrow = wr * 32 + mi * 16 + half * 8 + (lane >> 2);
            int r = rows_s[mrow];
            if (r < 0) continue;
            float* outp = Out + (size_t)r * N;
            #pragma unroll
            for (int ni = 0; ni < 8; ni++) {
                int col = n0 + wc * 64 + ni * 8 + ((lane & 3) << 1);
                float v0 = acc[mi][ni][half * 2 + 0] + bias[col];
                float v1 = acc[mi][ni][half * 2 + 1] + bias[col + 1];
                if (GELU) {
                    v0 = 0.5f * v0 * (1.0f + erff(v0 * 0.7071067811865475f));
                    v1 = 0.5f * v1 * (1.0f + erff(v1 * 0.7071067811865475f));
                }
                *(float2*)(outp + col) = make_float2(v0, v1);
            }
        }
    }
}

// ---------------------------------------------------------------------------
// LayerNorm over D=1024 (unchanged)
// ---------------------------------------------------------------------------
__global__ __launch_bounds__(256)
void layernorm_k(const int* __restrict__ ei,
                 const float* __restrict__ ln_g, const float* __restrict__ ln_b,
                 float* __restrict__ mid)
{
    int r = blockIdx.x;
    int e = ei[r];
    float* x = mid + (size_t)r * D_;
    int t = threadIdx.x;

    float v[4];
    float s = 0.f, ss = 0.f;
    #pragma unroll
    for (int i = 0; i < 4; i++) {
        v[i] = x[t + i * 256];
        s += v[i];
        ss += v[i] * v[i];
    }
    #pragma unroll
    for (int o = 16; o; o >>= 1) {
        s  += __shfl_xor_sync(0xffffffffu, s,  o);
        ss += __shfl_xor_sync(0xffffffffu, ss, o);
    }
    __shared__ float red[2][8];
    int w = t >> 5, l = t & 31;
    if (l == 0) { red[0][w] = s; red[1][w] = ss; }
    __syncthreads();
    float S = 0.f, SS = 0.f;
    #pragma unroll
    for (int i = 0; i < 8; i++) { S += red[0][i]; SS += red[1][i]; }

    float mu  = S * (1.0f / D_);
    float var = SS * (1.0f / D_) - mu * mu;
    float rstd = rsqrtf(var + LN_EPS);

    const float* gg = ln_g + (size_t)e * D_;
    const float* bb = ln_b + (size_t)e * D_;
    #pragma unroll
    for (int i = 0; i < 4; i++) {
        int c = t + i * 256;
        x[c] = (v[i] - mu) * rstd * gg[c] + bb[c];
    }
}

// ---------------------------------------------------------------------------
extern "C" void kernel_launch(void* const* d_in, const int* in_sizes, int n_in,
                              void* d_out, int out_size)
{
    const float* x   = (const float*)d_in[0];
    const int*   hp  = (const int*)d_in[1];
    const int*   ei  = (const int*)d_in[2];
    const float* pw1 = (const float*)d_in[3];
    const float* pb1 = (const float*)d_in[4];
    const float* pw2 = (const float*)d_in[5];
    const float* pb2 = (const float*)d_in[6];
    const float* qw1 = (const float*)d_in[7];
    const float* qb1 = (const float*)d_in[8];
    const float* qw2 = (const float*)d_in[9];
    const float* qb2 = (const float*)d_in[10];
    const float* lng = (const float*)d_in[11];
    const float* lnb = (const float*)d_in[12];
    const float* tw1 = (const float*)d_in[13];
    const float* tb1 = (const float*)d_in[14];
    const float* tw2 = (const float*)d_in[15];
    const float* tb2 = (const float*)d_in[16];
    float* out = (float*)d_out;

    float *h1, *mid, *h2;
    cudaGetSymbolAddress((void**)&h1,  g_h1);
    cudaGetSymbolAddress((void**)&mid, g_mid);
    cudaGetSymbolAddress((void**)&h2,  g_h2);

    static bool attr_done = false;
    if (!attr_done) {
        cudaFuncSetAttribute(gemm_tc<true >, cudaFuncAttributeMaxDynamicSharedMemorySize, SMEM_BYTES);
        cudaFuncSetAttribute(gemm_tc<false>, cudaFuncAttributeMaxDynamicSharedMemorySize, SMEM_BYTES);
        attr_done = true;
    }

    build_groups<<<1, 256>>>(hp, ei);

    // Stage 1: h1 = gelu(x @ {p,q}w1 + b1)     K=64
    gemm_tc<true ><<<dim3(H_ / TN, MTILES), 256, SMEM_BYTES>>>(x,   S_, H_, pw1, qw1, pb1, qb1, h1);
    // Stage 2: mid = h1 @ {p,q}w2 + b2         K=2048
    gemm_tc<false><<<dim3(D_ / TN, MTILES), 256, SMEM_BYTES>>>(h1,  H_, D_, pw2, qw2, pb2, qb2, mid);
    // Stage 3: layernorm in place
    layernorm_k<<<B_, 256>>>(ei, lng, lnb, mid);
    // Stage 4: h2 = gelu(mid @ tw1 + tb1)      K=1024
    gemm_tc<true ><<<dim3(H_ / TN, MTILES), 256, SMEM_BYTES>>>(mid, D_, H_, tw1, tw1, tb1, tb1, h2);
    // Stage 5: out = h2 @ tw2 + tb2            K=2048
    gemm_tc<false><<<dim3(D_ / TN, MTILES), 256, SMEM_BYTES>>>(h2,  H_, D_, tw2, tw2, tb2, tb2, out);
}

// round 10
// speedup vs baseline: 3.2140x; 1.2034x over previous
#include <cuda_runtime.h>
#include <cuda_fp16.h>
#include <math.h>
#include <stdint.h>
#include <cstdint>
#include <cstddef>

// Problem dims
#define E_ 8
#define S_ 64
#define H_ 2048
#define D_ 1024
#define B_ 8192
#define LN_EPS 1e-5f

// GEMM tiling
#define TM 128
#define TN 128
#define TKK 32                          // K per mainloop iteration
#define NGROUPS 16                      // (expert, sel) pairs
#define P_MAX (B_ + NGROUPS * TM)       // padded permuted length = 10240
#define MTILES (P_MAX / TM)             // 80

#define LDA_S 40                        // As row stride in fp16 (32 + 8 pad)
#define LDB_S 136                       // Bs row stride in fp16 (128 + 8 pad)

// Dynamic smem layout (elements): A has hi+lo planes, B hi only.
#define A_PL (TM * LDA_S)               // 5120 fp16 per A plane per buffer
#define B_PL (TKK * LDB_S)              // 4352 fp16 per B plane per buffer
#define OFF_AS_HI 0
#define OFF_AS_LO (OFF_AS_HI + 2 * A_PL)
#define OFF_BS_HI (OFF_AS_LO + 2 * A_PL)
#define SMEM_H_TOT (OFF_BS_HI + 2 * B_PL)             // in fp16 elements
#define SMEM_BYTES (SMEM_H_TOT * 2 + TM * 4)          // + rows_s ints

// Scratch (device globals — no allocation allowed)
__device__ int   g_perm[P_MAX];
__device__ int   g_tile_group[MTILES];
__device__ float g_h1[(size_t)B_ * H_];
__device__ float g_mid[(size_t)B_ * D_];
__device__ float g_h2[(size_t)B_ * H_];

// ---------------------------------------------------------------------------
// Group builder: group = expert*2 + has_proprio; rows packed contiguously at
// TM-aligned offsets; padding slots = -1.
// ---------------------------------------------------------------------------
__global__ void build_groups(const int* __restrict__ hp, const int* __restrict__ ei)
{
    __shared__ int cnt[NGROUPS];
    __shared__ int cur[NGROUPS];
    int t = threadIdx.x;
    if (t < NGROUPS) cnt[t] = 0;
    __syncthreads();

    for (int r = t; r < B_; r += blockDim.x) {
        int g = ei[r] * 2 + (hp[r] != 0);
        atomicAdd(&cnt[g], 1);
    }
    for (int i = t; i < P_MAX; i += blockDim.x) g_perm[i] = -1;
    __syncthreads();

    if (t == 0) {
        int off = 0;
        for (int g = 0; g < NGROUPS; g++) {
            cur[g] = off;
            int ntile = (cnt[g] + TM - 1) / TM;
            int t0 = off / TM;
            for (int k = 0; k < ntile; k++) g_tile_group[t0 + k] = g;
            off += ntile * TM;
        }
        for (int k = off / TM; k < MTILES; k++) g_tile_group[k] = -1;
    }
    __syncthreads();

    for (int r = t; r < B_; r += blockDim.x) {
        int g = ei[r] * 2 + (hp[r] != 0);
        int pos = atomicAdd(&cur[g], 1);
        g_perm[pos] = r;
    }
}

// ---------------------------------------------------------------------------
// PTX helpers
// ---------------------------------------------------------------------------
__device__ __forceinline__ void ldsm_x4(uint32_t* r, uint32_t addr) {
    asm volatile("ldmatrix.sync.aligned.m8n8.x4.shared.b16 {%0,%1,%2,%3}, [%4];\n"
                 : "=r"(r[0]), "=r"(r[1]), "=r"(r[2]), "=r"(r[3]) : "r"(addr));
}
__device__ __forceinline__ void ldsm_x4_t(uint32_t* r, uint32_t addr) {
    asm volatile("ldmatrix.sync.aligned.m8n8.x4.trans.shared.b16 {%0,%1,%2,%3}, [%4];\n"
                 : "=r"(r[0]), "=r"(r[1]), "=r"(r[2]), "=r"(r[3]) : "r"(addr));
}
__device__ __forceinline__ void mma_fp16(float* c, const uint32_t* a,
                                         uint32_t b0, uint32_t b1) {
    asm volatile("mma.sync.aligned.m16n8k16.row.col.f32.f16.f16.f32 "
                 "{%0,%1,%2,%3}, {%4,%5,%6,%7}, {%8,%9}, {%0,%1,%2,%3};\n"
                 : "+f"(c[0]), "+f"(c[1]), "+f"(c[2]), "+f"(c[3])
                 : "r"(a[0]), "r"(a[1]), "r"(a[2]), "r"(a[3]), "r"(b0), "r"(b1));
}
__device__ __forceinline__ void split_fp16(float a, __half& hi, __half& lo) {
    hi = __float2half_rn(a);
    lo = __float2half_rn(a - __half2float(hi));
}

// ---------------------------------------------------------------------------
// Grouped GEMM, fp16 tensor-core path: A split 2-term (ah+al), B single fp16.
// D = (ah + al) @ bh  — exact A, B at fp16 precision.
// Ping-pong double-buffered smem, one __syncthreads per K-tile.
// Block tile 128x128xTKK, 256 threads = 8 warps, warp tile 32x64.
// ---------------------------------------------------------------------------
template<bool GELU>
__global__ __launch_bounds__(256, 2)
void gemm_tc(const float* __restrict__ A, int K, int N,
             const float* __restrict__ Wp, const float* __restrict__ Wq,
             const float* __restrict__ bp, const float* __restrict__ bq,
             float* __restrict__ Out)
{
    int mt = blockIdx.y;
    int g = g_tile_group[mt];
    if (g < 0) return;
    int e = g >> 1, sel = g & 1;
    const float* W    = (sel ? Wq : Wp) + (size_t)e * K * N;
    const float* bias = (sel ? bq : bp) + (size_t)e * N;
    int n0 = blockIdx.x * TN;

    extern __shared__ __align__(16) __half dsm[];
    __half* As_hi = dsm + OFF_AS_HI;
    __half* As_lo = dsm + OFF_AS_LO;
    __half* Bs_hi = dsm + OFF_BS_HI;
    int* rows_s = (int*)(dsm + SMEM_H_TOT);

    int t = threadIdx.x;
    if (t < TM) rows_s[t] = g_perm[mt * TM + t];
    __syncthreads();

    int lane = t & 31;
    int wid  = t >> 5;
    int wr = wid & 3;          // M:  4 warps * 32
    int wc = wid >> 2;         // N:  2 warps * 64

    uint32_t as_hi_u = (uint32_t)__cvta_generic_to_shared(As_hi);
    uint32_t as_lo_u = (uint32_t)__cvta_generic_to_shared(As_lo);
    uint32_t bs_hi_u = (uint32_t)__cvta_generic_to_shared(Bs_hi);

    // Loader mappings
    int ia_row = t >> 1;                    // 0..127
    int ia_col = (t & 1) << 4;              // 0 or 16
    int rowA = rows_s[ia_row];
    const float* Ap = (rowA >= 0) ? A + (size_t)rowA * K + ia_col : (const float*)0;

    int ib_k = t >> 3;                      // 0..31
    int ib_n = (t & 7) << 4;                // 0..112
    const float* Bp = W + (size_t)ib_k * N + n0 + ib_n;

    // ldmatrix address components
    int a_row_off = lane & 15;
    int a_col_off = (lane >> 4) << 3;       // 0 or 8
    int bm = lane >> 3;
    int b_krow_off = ((bm & 1) << 3) + (lane & 7);
    int b_ncol_off = (bm >> 1) << 3;

    float acc[2][8][4];
    #pragma unroll
    for (int mi = 0; mi < 2; mi++)
        #pragma unroll
        for (int ni = 0; ni < 8; ni++)
            #pragma unroll
            for (int q = 0; q < 4; q++) acc[mi][ni][q] = 0.0f;

    // ---- helpers as lambdas ----
    auto load_tile = [&](int k0, float* va, float* vb) {
        #pragma unroll
        for (int i = 0; i < 4; i++) {
            float4 v = Ap ? *(const float4*)(Ap + k0 + i * 4)
                          : make_float4(0.f, 0.f, 0.f, 0.f);
            va[i*4+0] = v.x; va[i*4+1] = v.y; va[i*4+2] = v.z; va[i*4+3] = v.w;
        }
        #pragma unroll
        for (int i = 0; i < 4; i++) {
            float4 v = *(const float4*)(Bp + (size_t)k0 * N + i * 4);
            vb[i*4+0] = v.x; vb[i*4+1] = v.y; vb[i*4+2] = v.z; vb[i*4+3] = v.w;
        }
    };
    auto store_tile = [&](int buf, const float* va, const float* vb) {
        __half h[16], l[16];
        #pragma unroll
        for (int i = 0; i < 16; i++) split_fp16(va[i], h[i], l[i]);
        uint4* dh = (uint4*)&As_hi[buf * A_PL + ia_row * LDA_S + ia_col];
        uint4* dl = (uint4*)&As_lo[buf * A_PL + ia_row * LDA_S + ia_col];
        dh[0] = *(uint4*)&h[0]; dh[1] = *(uint4*)&h[8];
        dl[0] = *(uint4*)&l[0]; dl[1] = *(uint4*)&l[8];
        #pragma unroll
        for (int i = 0; i < 16; i++) h[i] = __float2half_rn(vb[i]);
        uint4* eh = (uint4*)&Bs_hi[buf * B_PL + ib_k * LDB_S + ib_n];
        eh[0] = *(uint4*)&h[0]; eh[1] = *(uint4*)&h[8];
    };

    // ---- prologue: fill buffer 0 ----
    float va[16], vb[16];
    load_tile(0, va, vb);
    store_tile(0, va, vb);
    __syncthreads();

    int nk = K / TKK;
    for (int it = 0; it < nk; it++) {
        int buf = it & 1;
        bool has_next = (it + 1) < nk;

        // issue next tile's gmem loads early (latency hidden by MMAs below)
        if (has_next) load_tile((it + 1) * TKK, va, vb);

        uint32_t aBaseHi = as_hi_u + (uint32_t)(buf * A_PL) * 2u;
        uint32_t aBaseLo = as_lo_u + (uint32_t)(buf * A_PL) * 2u;
        uint32_t bBaseHi = bs_hi_u + (uint32_t)(buf * B_PL) * 2u;

        #pragma unroll
        for (int ks = 0; ks < 2; ks++) {
            uint32_t a_hi[2][4], a_lo[2][4], bfr[4];
            #pragma unroll
            for (int mi = 0; mi < 2; mi++) {
                int row = wr * 32 + mi * 16 + a_row_off;
                int cb  = ks * 16 + a_col_off;
                uint32_t off = (uint32_t)(row * LDA_S + cb) * 2u;
                ldsm_x4(a_hi[mi], aBaseHi + off);
                ldsm_x4(a_lo[mi], aBaseLo + off);
            }
            int krow = ks * 16 + b_krow_off;
            #pragma unroll
            for (int j = 0; j < 4; j++) {
                int ncol = wc * 64 + j * 16 + b_ncol_off;
                uint32_t off = (uint32_t)(krow * LDB_S + ncol) * 2u;
                ldsm_x4_t(bfr, bBaseHi + off);
                #pragma unroll
                for (int mi = 0; mi < 2; mi++) {
                    mma_fp16(acc[mi][2*j+0], a_hi[mi], bfr[0], bfr[1]);
                    mma_fp16(acc[mi][2*j+1], a_hi[mi], bfr[2], bfr[3]);
                    mma_fp16(acc[mi][2*j+0], a_lo[mi], bfr[0], bfr[1]);
                    mma_fp16(acc[mi][2*j+1], a_lo[mi], bfr[2], bfr[3]);
                }
            }
        }

        // convert + store next tile into the other buffer
        if (has_next) store_tile(buf ^ 1, va, vb);
        __syncthreads();
    }

    // ---- epilogue: bias (+ exact-erf GELU), scatter to original rows ----
    #pragma unroll
    for (int mi = 0; mi < 2; mi++) {
        #pragma unroll
        for (int half = 0; half < 2; half++) {
            int mrow = wr * 32 + mi * 16 + half * 8 + (lane >> 2);
            int r = rows_s[mrow];
            if (r < 0) continue;
            float* outp = Out + (size_t)r * N;
            #pragma unroll
            for (int ni = 0; ni < 8; ni++) {
                int col = n0 + wc * 64 + ni * 8 + ((lane & 3) << 1);
                float v0 = acc[mi][ni][half * 2 + 0] + bias[col];
                float v1 = acc[mi][ni][half * 2 + 1] + bias[col + 1];
                if (GELU) {
                    v0 = 0.5f * v0 * (1.0f + erff(v0 * 0.7071067811865475f));
                    v1 = 0.5f * v1 * (1.0f + erff(v1 * 0.7071067811865475f));
                }
                *(float2*)(outp + col) = make_float2(v0, v1);
            }
        }
    }
}

// ---------------------------------------------------------------------------
// LayerNorm over D=1024 (unchanged)
// ---------------------------------------------------------------------------
__global__ __launch_bounds__(256)
void layernorm_k(const int* __restrict__ ei,
                 const float* __restrict__ ln_g, const float* __restrict__ ln_b,
                 float* __restrict__ mid)
{
    int r = blockIdx.x;
    int e = ei[r];
    float* x = mid + (size_t)r * D_;
    int t = threadIdx.x;

    float v[4];
    float s = 0.f, ss = 0.f;
    #pragma unroll
    for (int i = 0; i < 4; i++) {
        v[i] = x[t + i * 256];
        s += v[i];
        ss += v[i] * v[i];
    }
    #pragma unroll
    for (int o = 16; o; o >>= 1) {
        s  += __shfl_xor_sync(0xffffffffu, s,  o);
        ss += __shfl_xor_sync(0xffffffffu, ss, o);
    }
    __shared__ float red[2][8];
    int w = t >> 5, l = t & 31;
    if (l == 0) { red[0][w] = s; red[1][w] = ss; }
    __syncthreads();
    float S = 0.f, SS = 0.f;
    #pragma unroll
    for (int i = 0; i < 8; i++) { S += red[0][i]; SS += red[1][i]; }

    float mu  = S * (1.0f / D_);
    float var = SS * (1.0f / D_) - mu * mu;
    float rstd = rsqrtf(var + LN_EPS);

    const float* gg = ln_g + (size_t)e * D_;
    const float* bb = ln_b + (size_t)e * D_;
    #pragma unroll
    for (int i = 0; i < 4; i++) {
        int c = t + i * 256;
        x[c] = (v[i] - mu) * rstd * gg[c] + bb[c];
    }
}

// ---------------------------------------------------------------------------
extern "C" void kernel_launch(void* const* d_in, const int* in_sizes, int n_in,
                              void* d_out, int out_size)
{
    const float* x   = (const float*)d_in[0];
    const int*   hp  = (const int*)d_in[1];
    const int*   ei  = (const int*)d_in[2];
    const float* pw1 = (const float*)d_in[3];
    const float* pb1 = (const float*)d_in[4];
    const float* pw2 = (const float*)d_in[5];
    const float* pb2 = (const float*)d_in[6];
    const float* qw1 = (const float*)d_in[7];
    const float* qb1 = (const float*)d_in[8];
    const float* qw2 = (const float*)d_in[9];
    const float* qb2 = (const float*)d_in[10];
    const float* lng = (const float*)d_in[11];
    const float* lnb = (const float*)d_in[12];
    const float* tw1 = (const float*)d_in[13];
    const float* tb1 = (const float*)d_in[14];
    const float* tw2 = (const float*)d_in[15];
    const float* tb2 = (const float*)d_in[16];
    float* out = (float*)d_out;

    float *h1, *mid, *h2;
    cudaGetSymbolAddress((void**)&h1,  g_h1);
    cudaGetSymbolAddress((void**)&mid, g_mid);
    cudaGetSymbolAddress((void**)&h2,  g_h2);

    static bool attr_done = false;
    if (!attr_done) {
        cudaFuncSetAttribute(gemm_tc<true >, cudaFuncAttributeMaxDynamicSharedMemorySize, SMEM_BYTES);
        cudaFuncSetAttribute(gemm_tc<false>, cudaFuncAttributeMaxDynamicSharedMemorySize, SMEM_BYTES);
        attr_done = true;
    }

    build_groups<<<1, 256>>>(hp, ei);

    // Stage 1: h1 = gelu(x @ {p,q}w1 + b1)     K=64
    gemm_tc<true ><<<dim3(H_ / TN, MTILES), 256, SMEM_BYTES>>>(x,   S_, H_, pw1, qw1, pb1, qb1, h1);
    // Stage 2: mid = h1 @ {p,q}w2 + b2         K=2048
    gemm_tc<false><<<dim3(D_ / TN, MTILES), 256, SMEM_BYTES>>>(h1,  H_, D_, pw2, qw2, pb2, qb2, mid);
    // Stage 3: layernorm in place
    layernorm_k<<<B_, 256>>>(ei, lng, lnb, mid);
    // Stage 4: h2 = gelu(mid @ tw1 + tb1)      K=1024
    gemm_tc<true ><<<dim3(H_ / TN, MTILES), 256, SMEM_BYTES>>>(mid, D_, H_, tw1, tw1, tb1, tb1, h2);
    // Stage 5: out = h2 @ tw2 + tb2            K=2048
    gemm_tc<false><<<dim3(D_ / TN, MTILES), 256, SMEM_BYTES>>>(h2,  H_, D_, tw2, tw2, tb2, tb2, out);
}

// round 12
// speedup vs baseline: 3.4790x; 1.0825x over previous
#include <cuda_runtime.h>
#include <cuda_fp16.h>
#include <math.h>
#include <stdint.h>
#include <cstdint>
#include <cstddef>

// Problem dims
#define E_ 8
#define S_ 64
#define H_ 2048
#define D_ 1024
#define B_ 8192
#define LN_EPS 1e-5f

// GEMM tiling
#define TM 128
#define TN 128
#define TKK 32
#define NGROUPS 16
#define P_MAX (B_ + NGROUPS * TM)       // 10240
#define MTILES (P_MAX / TM)             // 80

#define LDA_S 40                        // As row stride in fp16 (32 + 8 pad)
#define LDB_S 136                       // Bs row stride in fp16 (128 + 8 pad)

// Dynamic smem layout (elements): A hi+lo planes, B hi only; 2 buffers.
#define A_PL (TM * LDA_S)               // 5120
#define B_PL (TKK * LDB_S)              // 4352
#define OFF_AS_HI 0
#define OFF_AS_LO (OFF_AS_HI + 2 * A_PL)
#define OFF_BS_HI (OFF_AS_LO + 2 * A_PL)
#define SMEM_H_TOT (OFF_BS_HI + 2 * B_PL)
#define SMEM_BYTES (SMEM_H_TOT * 2 + TM * 4)

// fp16 weight buffer offsets (in halfs)
#define WH_PW1 0
#define WH_QW1 (WH_PW1 + E_ * S_ * H_)          // 1048576
#define WH_PW2 (WH_QW1 + E_ * S_ * H_)          // 2097152
#define WH_QW2 (WH_PW2 + E_ * H_ * D_)          // 18874368
#define WH_TW1 (WH_QW2 + E_ * H_ * D_)          // 35651584
#define WH_TW2 (WH_TW1 + E_ * D_ * H_)          // 52428800
#define WH_TOT (WH_TW2 + E_ * H_ * D_)          // 69206016

// Scratch (device globals — no allocation allowed)
__device__ int    g_perm[P_MAX];
__device__ int    g_tile_group[MTILES];
__device__ __half g_wh[WH_TOT];                       // 138 MB fp16 weights
__device__ __half g_h1h[(size_t)B_ * H_];             // 32 MB
__device__ __half g_h1l[(size_t)B_ * H_];
__device__ __half g_h2h[(size_t)B_ * H_];
__device__ __half g_h2l[(size_t)B_ * H_];
__device__ __half g_midh[(size_t)B_ * D_];            // 16 MB
__device__ __half g_midl[(size_t)B_ * D_];
__device__ float  g_mid[(size_t)B_ * D_];             // 32 MB

// ---------------------------------------------------------------------------
// Group builder
// ---------------------------------------------------------------------------
__global__ void build_groups(const int* __restrict__ hp, const int* __restrict__ ei)
{
    __shared__ int cnt[NGROUPS];
    __shared__ int cur[NGROUPS];
    int t = threadIdx.x;
    if (t < NGROUPS) cnt[t] = 0;
    __syncthreads();

    for (int r = t; r < B_; r += blockDim.x) {
        int g = ei[r] * 2 + (hp[r] != 0);
        atomicAdd(&cnt[g], 1);
    }
    for (int i = t; i < P_MAX; i += blockDim.x) g_perm[i] = -1;
    __syncthreads();

    if (t == 0) {
        int off = 0;
        for (int g = 0; g < NGROUPS; g++) {
            cur[g] = off;
            int ntile = (cnt[g] + TM - 1) / TM;
            int t0 = off / TM;
            for (int k = 0; k < ntile; k++) g_tile_group[t0 + k] = g;
            off += ntile * TM;
        }
        for (int k = off / TM; k < MTILES; k++) g_tile_group[k] = -1;
    }
    __syncthreads();

    for (int r = t; r < B_; r += blockDim.x) {
        int g = ei[r] * 2 + (hp[r] != 0);
        int pos = atomicAdd(&cur[g], 1);
        g_perm[pos] = r;
    }
}

// ---------------------------------------------------------------------------
// Weight fp32 -> fp16 conversion (grid-stride, float4 vectorized)
// ---------------------------------------------------------------------------
__global__ void convert_w(const float* __restrict__ src, __half* __restrict__ dst, int n4)
{
    int i = blockIdx.x * blockDim.x + threadIdx.x;
    int stride = gridDim.x * blockDim.x;
    const float4* s = (const float4*)src;
    for (; i < n4; i += stride) {
        float4 v = s[i];
        __half h[4];
        h[0] = __float2half_rn(v.x); h[1] = __float2half_rn(v.y);
        h[2] = __float2half_rn(v.z); h[3] = __float2half_rn(v.w);
        *(uint2*)(dst + (size_t)4 * i) = *(uint2*)h;
    }
}

// ---------------------------------------------------------------------------
// PTX helpers
// ---------------------------------------------------------------------------
__device__ __forceinline__ void ldsm_x4(uint32_t* r, uint32_t addr) {
    asm volatile("ldmatrix.sync.aligned.m8n8.x4.shared.b16 {%0,%1,%2,%3}, [%4];\n"
                 : "=r"(r[0]), "=r"(r[1]), "=r"(r[2]), "=r"(r[3]) : "r"(addr));
}
__device__ __forceinline__ void ldsm_x4_t(uint32_t* r, uint32_t addr) {
    asm volatile("ldmatrix.sync.aligned.m8n8.x4.trans.shared.b16 {%0,%1,%2,%3}, [%4];\n"
                 : "=r"(r[0]), "=r"(r[1]), "=r"(r[2]), "=r"(r[3]) : "r"(addr));
}
__device__ __forceinline__ void mma_fp16(float* c, const uint32_t* a,
                                         uint32_t b0, uint32_t b1) {
    asm volatile("mma.sync.aligned.m16n8k16.row.col.f32.f16.f16.f32 "
                 "{%0,%1,%2,%3}, {%4,%5,%6,%7}, {%8,%9}, {%0,%1,%2,%3};\n"
                 : "+f"(c[0]), "+f"(c[1]), "+f"(c[2]), "+f"(c[3])
                 : "r"(a[0]), "r"(a[1]), "r"(a[2]), "r"(a[3]), "r"(b0), "r"(b1));
}
__device__ __forceinline__ void split_fp16(float a, __half& hi, __half& lo) {
    hi = __float2half_rn(a);
    lo = __float2half_rn(a - __half2float(hi));
}
__device__ __forceinline__ void cp16(uint32_t d, const void* s) {
    asm volatile("cp.async.cg.shared.global [%0], [%1], 16;" :: "r"(d), "l"(s));
}
__device__ __forceinline__ void cp16z(uint32_t d, const void* s, uint32_t sz) {
    asm volatile("cp.async.cg.shared.global [%0], [%1], 16, %2;" :: "r"(d), "l"(s), "r"(sz));
}
#define CP_COMMIT() asm volatile("cp.async.commit_group;" ::: "memory")
#define CP_WAIT0()  asm volatile("cp.async.wait_group 0;" ::: "memory")

// ---------------------------------------------------------------------------
// Grouped GEMM, fp16 tensor cores. A = (ah + al) exact 2-term; B single fp16.
// A16: A read from pre-split fp16 planes via cp.async (else fp32 + in-kernel
// split, stage 1 only). OUT16: write pre-split fp16 planes (for next stage).
// Block tile 128x128x32, 256 threads = 8 warps, warp tile 32x64.
// ---------------------------------------------------------------------------
template<bool GELU, bool A16, bool OUT16>
__global__ __launch_bounds__(256, 2)
void gemm_tc(const float* __restrict__ Af,
             const __half* __restrict__ Ah, const __half* __restrict__ Al,
             int K, int N,
             const __half* __restrict__ Wp, const __half* __restrict__ Wq,
             const float* __restrict__ bp, const float* __restrict__ bq,
             float* __restrict__ OutF,
             __half* __restrict__ OutH, __half* __restrict__ OutL)
{
    int mt = blockIdx.y;
    int g = g_tile_group[mt];
    if (g < 0) return;
    int e = g >> 1, sel = g & 1;
    const __half* W   = (sel ? Wq : Wp) + (size_t)e * K * N;
    const float* bias = (sel ? bq : bp) + (size_t)e * N;
    int n0 = blockIdx.x * TN;

    extern __shared__ __align__(16) __half dsm[];
    __half* As_hi = dsm + OFF_AS_HI;
    __half* As_lo = dsm + OFF_AS_LO;
    __half* Bs_hi = dsm + OFF_BS_HI;
    int* rows_s = (int*)(dsm + SMEM_H_TOT);

    int t = threadIdx.x;
    if (t < TM) rows_s[t] = g_perm[mt * TM + t];
    __syncthreads();

    int lane = t & 31;
    int wid  = t >> 5;
    int wr = wid & 3;
    int wc = wid >> 2;

    uint32_t as_hi_u = (uint32_t)__cvta_generic_to_shared(As_hi);
    uint32_t as_lo_u = (uint32_t)__cvta_generic_to_shared(As_lo);
    uint32_t bs_hi_u = (uint32_t)__cvta_generic_to_shared(Bs_hi);

    // Loader mappings
    int ia_row = t >> 1;                    // 0..127
    int ia_col = (t & 1) << 4;              // 0 or 16 (halfs)
    int rowA = rows_s[ia_row];
    uint32_t szA = (rowA >= 0) ? 16u : 0u;
    const __half* Ah_p = (rowA >= 0) ? Ah + (size_t)rowA * K + ia_col : Ah;
    const __half* Al_p = (rowA >= 0) ? Al + (size_t)rowA * K + ia_col : Al;
    const float*  Af_p = (rowA >= 0 && !A16) ? Af + (size_t)rowA * K + ia_col : (const float*)0;

    int ib_k = t >> 3;                      // 0..31
    int ib_n = (t & 7) << 4;                // 0..112 (halfs)
    const __half* Bp = W + (size_t)ib_k * N + n0 + ib_n;

    uint32_t dA_off = (uint32_t)(ia_row * LDA_S + ia_col) * 2u;
    uint32_t dB_off = (uint32_t)(ib_k * LDB_S + ib_n) * 2u;

    // ldmatrix address components
    int a_row_off = lane & 15;
    int a_col_off = (lane >> 4) << 3;
    int bm = lane >> 3;
    int b_krow_off = ((bm & 1) << 3) + (lane & 7);
    int b_ncol_off = (bm >> 1) << 3;

    float acc[2][8][4];
    #pragma unroll
    for (int mi = 0; mi < 2; mi++)
        #pragma unroll
        for (int ni = 0; ni < 8; ni++)
            #pragma unroll
            for (int q = 0; q < 4; q++) acc[mi][ni][q] = 0.0f;

    auto issue_tile = [&](int buf, int k0) {
        uint32_t dh = as_hi_u + (uint32_t)(buf * A_PL) * 2u + dA_off;
        uint32_t dl = as_lo_u + (uint32_t)(buf * A_PL) * 2u + dA_off;
        cp16z(dh,      Ah_p + k0,     szA);
        cp16z(dh + 16, Ah_p + k0 + 8, szA);
        cp16z(dl,      Al_p + k0,     szA);
        cp16z(dl + 16, Al_p + k0 + 8, szA);
        uint32_t db = bs_hi_u + (uint32_t)(buf * B_PL) * 2u + dB_off;
        const __half* sB = Bp + (size_t)k0 * N;
        cp16(db,      sB);
        cp16(db + 16, sB + 8);
    };

    auto compute = [&](int buf) {
        uint32_t aBaseHi = as_hi_u + (uint32_t)(buf * A_PL) * 2u;
        uint32_t aBaseLo = as_lo_u + (uint32_t)(buf * A_PL) * 2u;
        uint32_t bBaseHi = bs_hi_u + (uint32_t)(buf * B_PL) * 2u;
        #pragma unroll
        for (int ks = 0; ks < 2; ks++) {
            uint32_t a_hi[2][4], a_lo[2][4], bfr[4];
            #pragma unroll
            for (int mi = 0; mi < 2; mi++) {
                int row = wr * 32 + mi * 16 + a_row_off;
                int cb  = ks * 16 + a_col_off;
                uint32_t off = (uint32_t)(row * LDA_S + cb) * 2u;
                ldsm_x4(a_hi[mi], aBaseHi + off);
                ldsm_x4(a_lo[mi], aBaseLo + off);
            }
            int krow = ks * 16 + b_krow_off;
            #pragma unroll
            for (int j = 0; j < 4; j++) {
                int ncol = wc * 64 + j * 16 + b_ncol_off;
                uint32_t off = (uint32_t)(krow * LDB_S + ncol) * 2u;
                ldsm_x4_t(bfr, bBaseHi + off);
                #pragma unroll
                for (int mi = 0; mi < 2; mi++) {
                    mma_fp16(acc[mi][2*j+0], a_hi[mi], bfr[0], bfr[1]);
                    mma_fp16(acc[mi][2*j+1], a_hi[mi], bfr[2], bfr[3]);
                    mma_fp16(acc[mi][2*j+0], a_lo[mi], bfr[0], bfr[1]);
                    mma_fp16(acc[mi][2*j+1], a_lo[mi], bfr[2], bfr[3]);
                }
            }
        }
    };

    int nk = K / TKK;

    if (A16) {
        // Fully async pipelined path
        issue_tile(0, 0); CP_COMMIT();
        CP_WAIT0(); __syncthreads();
        for (int it = 0; it < nk; it++) {
            int buf = it & 1;
            bool hn = (it + 1) < nk;
            if (hn) { issue_tile(buf ^ 1, (it + 1) * TKK); CP_COMMIT(); }
            compute(buf);
            if (hn) CP_WAIT0();
            __syncthreads();
        }
    } else {
        // fp32-A path (stage 1 only, K=64): register split for A, cp.async B.
        for (int it = 0; it < nk; it++) {
            int k0 = it * TKK;
            float va[16];
            #pragma unroll
            for (int i = 0; i < 4; i++) {
                float4 v = Af_p ? *(const float4*)(Af_p + k0 + i * 4)
                                : make_float4(0.f, 0.f, 0.f, 0.f);
                va[i*4+0] = v.x; va[i*4+1] = v.y; va[i*4+2] = v.z; va[i*4+3] = v.w;
            }
            uint32_t db = bs_hi_u + dB_off;
            const __half* sB = Bp + (size_t)k0 * N;
            cp16(db, sB); cp16(db + 16, sB + 8);
            CP_COMMIT();

            __half h[16], l[16];
            #pragma unroll
            for (int i = 0; i < 16; i++) split_fp16(va[i], h[i], l[i]);
            uint4* dh = (uint4*)&As_hi[ia_row * LDA_S + ia_col];
            uint4* dl = (uint4*)&As_lo[ia_row * LDA_S + ia_col];
            dh[0] = *(uint4*)&h[0]; dh[1] = *(uint4*)&h[8];
            dl[0] = *(uint4*)&l[0]; dl[1] = *(uint4*)&l[8];

            CP_WAIT0();
            __syncthreads();
            compute(0);
            __syncthreads();
        }
    }

    // ---- epilogue ----
    #pragma unroll
    for (int mi = 0; mi < 2; mi++) {
        #pragma unroll
        for (int half = 0; half < 2; half++) {
            int mrow = wr * 32 + mi * 16 + half * 8 + (lane >> 2);
            int r = rows_s[mrow];
            if (r < 0) continue;
            #pragma unroll
            for (int ni = 0; ni < 8; ni++) {
                int col = n0 + wc * 64 + ni * 8 + ((lane & 3) << 1);
                float v0 = acc[mi][ni][half * 2 + 0] + bias[col];
                float v1 = acc[mi][ni][half * 2 + 1] + bias[col + 1];
                if (GELU) {
                    v0 = 0.5f * v0 * (1.0f + erff(v0 * 0.7071067811865475f));
                    v1 = 0.5f * v1 * (1.0f + erff(v1 * 0.7071067811865475f));
                }
                if (OUT16) {
                    __half h0, l0, h1, l1;
                    split_fp16(v0, h0, l0);
                    split_fp16(v1, h1, l1);
                    __half hh[2] = {h0, h1};
                    __half ll[2] = {l0, l1};
                    *(uint32_t*)(OutH + (size_t)r * N + col) = *(uint32_t*)hh;
                    *(uint32_t*)(OutL + (size_t)r * N + col) = *(uint32_t*)ll;
                } else {
                    *(float2*)(OutF + (size_t)r * N + col) = make_float2(v0, v1);
                }
            }
        }
    }
}

// ---------------------------------------------------------------------------
// LayerNorm over D=1024; reads fp32 mid, writes pre-split fp16 planes.
// ---------------------------------------------------------------------------
__global__ __launch_bounds__(256)
void layernorm_k(const int* __restrict__ ei,
                 const float* __restrict__ ln_g, const float* __restrict__ ln_b,
                 const float* __restrict__ mid,
                 __half* __restrict__ outh, __half* __restrict__ outl)
{
    int r = blockIdx.x;
    int e = ei[r];
    const float* x = mid + (size_t)r * D_;
    int t = threadIdx.x;

    float v[4];
    float s = 0.f, ss = 0.f;
    #pragma unroll
    for (int i = 0; i < 4; i++) {
        v[i] = x[t + i * 256];
        s += v[i];
        ss += v[i] * v[i];
    }
    #pragma unroll
    for (int o = 16; o; o >>= 1) {
        s  += __shfl_xor_sync(0xffffffffu, s,  o);
        ss += __shfl_xor_sync(0xffffffffu, ss, o);
    }
    __shared__ float red[2][8];
    int w = t >> 5, l = t & 31;
    if (l == 0) { red[0][w] = s; red[1][w] = ss; }
    __syncthreads();
    float S = 0.f, SS = 0.f;
    #pragma unroll
    for (int i = 0; i < 8; i++) { S += red[0][i]; SS += red[1][i]; }

    float mu  = S * (1.0f / D_);
    float var = SS * (1.0f / D_) - mu * mu;
    float rstd = rsqrtf(var + LN_EPS);

    const float* gg = ln_g + (size_t)e * D_;
    const float* bb = ln_b + (size_t)e * D_;
    #pragma unroll
    for (int i = 0; i < 4; i++) {
        int c = t + i * 256;
        float y = (v[i] - mu) * rstd * gg[c] + bb[c];
        __half hi, lo;
        split_fp16(y, hi, lo);
        outh[(size_t)r * D_ + c] = hi;
        outl[(size_t)r * D_ + c] = lo;
    }
}

// ---------------------------------------------------------------------------
extern "C" void kernel_launch(void* const* d_in, const int* in_sizes, int n_in,
                              void* d_out, int out_size)
{
    const float* x   = (const float*)d_in[0];
    const int*   hp  = (const int*)d_in[1];
    const int*   ei  = (const int*)d_in[2];
    const float* pw1 = (const float*)d_in[3];
    const float* pb1 = (const float*)d_in[4];
    const float* pw2 = (const float*)d_in[5];
    const float* pb2 = (const float*)d_in[6];
    const float* qw1 = (const float*)d_in[7];
    const float* qb1 = (const float*)d_in[8];
    const float* qw2 = (const float*)d_in[9];
    const float* qb2 = (const float*)d_in[10];
    const float* lng = (const float*)d_in[11];
    const float* lnb = (const float*)d_in[12];
    const float* tw1 = (const float*)d_in[13];
    const float* tb1 = (const float*)d_in[14];
    const float* tw2 = (const float*)d_in[15];
    const float* tb2 = (const float*)d_in[16];
    float* out = (float*)d_out;

    __half *wh, *h1h, *h1l, *h2h, *h2l, *midh, *midl;
    float *mid;
    cudaGetSymbolAddress((void**)&wh,   g_wh);
    cudaGetSymbolAddress((void**)&h1h,  g_h1h);
    cudaGetSymbolAddress((void**)&h1l,  g_h1l);
    cudaGetSymbolAddress((void**)&h2h,  g_h2h);
    cudaGetSymbolAddress((void**)&h2l,  g_h2l);
    cudaGetSymbolAddress((void**)&midh, g_midh);
    cudaGetSymbolAddress((void**)&midl, g_midl);
    cudaGetSymbolAddress((void**)&mid,  g_mid);

    static bool attr_done = false;
    if (!attr_done) {
        cudaFuncSetAttribute(gemm_tc<true , false, true >, cudaFuncAttributeMaxDynamicSharedMemorySize, SMEM_BYTES);
        cudaFuncSetAttribute(gemm_tc<false, true , false>, cudaFuncAttributeMaxDynamicSharedMemorySize, SMEM_BYTES);
        cudaFuncSetAttribute(gemm_tc<true , true , true >, cudaFuncAttributeMaxDynamicSharedMemorySize, SMEM_BYTES);
        attr_done = true;
    }

    // Weight conversion (fp32 -> fp16), once per launch
    {
        int n4s = E_ * S_ * H_ / 4;        // 262144
        int n4b = E_ * H_ * D_ / 4;        // 4194304
        convert_w<<<(n4s + 255) / 256, 256>>>(pw1, wh + WH_PW1, n4s);
        convert_w<<<(n4s + 255) / 256, 256>>>(qw1, wh + WH_QW1, n4s);
        convert_w<<<4096, 256>>>(pw2, wh + WH_PW2, n4b);
        convert_w<<<4096, 256>>>(qw2, wh + WH_QW2, n4b);
        convert_w<<<4096, 256>>>(tw1, wh + WH_TW1, n4b);
        convert_w<<<4096, 256>>>(tw2, wh + WH_TW2, n4b);
    }

    build_groups<<<1, 256>>>(hp, ei);

    // Stage 1: h1(planes) = gelu(x @ {p,q}w1 + b1)     K=64, fp32 A
    gemm_tc<true , false, true ><<<dim3(H_ / TN, MTILES), 256, SMEM_BYTES>>>(
        x, (const __half*)0, (const __half*)0, S_, H_,
        wh + WH_PW1, wh + WH_QW1, pb1, qb1,
        (float*)0, h1h, h1l);
    // Stage 2: mid = h1 @ {p,q}w2 + b2                 K=2048
    gemm_tc<false, true , false><<<dim3(D_ / TN, MTILES), 256, SMEM_BYTES>>>(
        (const float*)0, h1h, h1l, H_, D_,
        wh + WH_PW2, wh + WH_QW2, pb2, qb2,
        mid, (__half*)0, (__half*)0);
    // Stage 3: layernorm -> mid planes
    layernorm_k<<<B_, 256>>>(ei, lng, lnb, mid, midh, midl);
    // Stage 4: h2(planes) = gelu(mid @ tw1 + tb1)      K=1024
    gemm_tc<true , true , true ><<<dim3(H_ / TN, MTILES), 256, SMEM_BYTES>>>(
        (const float*)0, midh, midl, D_, H_,
        wh + WH_TW1, wh + WH_TW1, tb1, tb1,
        (float*)0, h2h, h2l);
    // Stage 5: out = h2 @ tw2 + tb2                    K=2048
    gemm_tc<false, true , false><<<dim3(D_ / TN, MTILES), 256, SMEM_BYTES>>>(
        (const float*)0, h2h, h2l, H_, D_,
        wh + WH_TW2, wh + WH_TW2, tb2, tb2,
        out, (__half*)0, (__half*)0);
}

// round 13
// speedup vs baseline: 3.5786x; 1.0286x over previous
#include <cuda_runtime.h>
#include <cuda_fp16.h>
#include <math.h>
#include <stdint.h>
#include <cstdint>
#include <cstddef>

// Problem dims
#define E_ 8
#define S_ 64
#define H_ 2048
#define D_ 1024
#define B_ 8192
#define LN_EPS 1e-5f

// GEMM tiling
#define TM 128
#define TN 128
#define TKK 32
#define NGROUPS 16
#define P_MAX (B_ + NGROUPS * TM)       // 10240
#define MTILES (P_MAX / TM)             // 80

#define LDA_S 40                        // As row stride in fp16 (32 + 8 pad)
#define LDB_S 136                       // Bs row stride in fp16 (128 + 8 pad)

// Dynamic smem layout (elements): A hi+lo planes, B hi only; 2 buffers.
#define A_PL (TM * LDA_S)               // 5120
#define B_PL (TKK * LDB_S)              // 4352
#define OFF_AS_HI 0
#define OFF_AS_LO (OFF_AS_HI + 2 * A_PL)
#define OFF_BS_HI (OFF_AS_LO + 2 * A_PL)
#define SMEM_H_TOT (OFF_BS_HI + 2 * B_PL)
#define SMEM_BYTES (SMEM_H_TOT * 2 + TM * 4)

// fp16 weight buffer offsets (in halfs)
#define WH_PW1 0
#define WH_QW1 (WH_PW1 + E_ * S_ * H_)
#define WH_PW2 (WH_QW1 + E_ * S_ * H_)
#define WH_QW2 (WH_PW2 + E_ * H_ * D_)
#define WH_TW1 (WH_QW2 + E_ * H_ * D_)
#define WH_TW2 (WH_TW1 + E_ * D_ * H_)
#define WH_TOT (WH_TW2 + E_ * H_ * D_)

#define N4_SMALL (E_ * S_ * H_ / 4)     // 262144 float4 per small weight
#define N4_BIG   (E_ * H_ * D_ / 4)     // 4194304 float4 per big weight

// Scratch (device globals — no allocation allowed)
__device__ int    g_perm[P_MAX];
__device__ int    g_tile_group[MTILES];
__device__ __half g_wh[WH_TOT];
__device__ __half g_h1h[(size_t)B_ * H_];
__device__ __half g_h1l[(size_t)B_ * H_];
__device__ __half g_h2h[(size_t)B_ * H_];
__device__ __half g_h2l[(size_t)B_ * H_];
__device__ __half g_midh[(size_t)B_ * D_];
__device__ __half g_midl[(size_t)B_ * D_];
__device__ float  g_mid[(size_t)B_ * D_];

// ---------------------------------------------------------------------------
// Shared converter body: pairs of (srcA->dstA, srcB->dstB), n4 float4 each,
// processed by `nblk` CTA-equivalents with id `cb`.
// ---------------------------------------------------------------------------
__device__ __forceinline__ void cvt_pair(int cb, int nblk, int tid,
                                         const float* srcA, __half* dstA,
                                         const float* srcB, __half* dstB, int n4)
{
    int half_blk = nblk >> 1;
    const float4* s;
    __half* d;
    int id;
    if (cb < half_blk) { s = (const float4*)srcA; d = dstA; id = cb; }
    else               { s = (const float4*)srcB; d = dstB; id = cb - half_blk; }
    int stride = half_blk * 256;
    for (int i = id * 256 + tid; i < n4; i += stride) {
        float4 v = s[i];
        __half h[4];
        h[0] = __float2half_rn(v.x); h[1] = __float2half_rn(v.y);
        h[2] = __float2half_rn(v.z); h[3] = __float2half_rn(v.w);
        *(uint2*)(d + (size_t)4 * i) = *(uint2*)h;
    }
}

// ---------------------------------------------------------------------------
// Group builder (block 0) + small-weight conversion (blocks 1..N).
// ---------------------------------------------------------------------------
__global__ void build_groups_cvt(const int* __restrict__ hp, const int* __restrict__ ei,
                                 const float* __restrict__ pw1, __half* __restrict__ pw1h,
                                 const float* __restrict__ qw1, __half* __restrict__ qw1h)
{
    int t = threadIdx.x;
    if (blockIdx.x > 0) {
        cvt_pair(blockIdx.x - 1, gridDim.x - 1, t, pw1, pw1h, qw1, qw1h, N4_SMALL);
        return;
    }

    __shared__ int cnt[NGROUPS];
    __shared__ int cur[NGROUPS];
    if (t < NGROUPS) cnt[t] = 0;
    __syncthreads();

    for (int r = t; r < B_; r += blockDim.x) {
        int g = ei[r] * 2 + (hp[r] != 0);
        atomicAdd(&cnt[g], 1);
    }
    for (int i = t; i < P_MAX; i += blockDim.x) g_perm[i] = -1;
    __syncthreads();

    if (t == 0) {
        int off = 0;
        for (int g = 0; g < NGROUPS; g++) {
            cur[g] = off;
            int ntile = (cnt[g] + TM - 1) / TM;
            int t0 = off / TM;
            for (int k = 0; k < ntile; k++) g_tile_group[t0 + k] = g;
            off += ntile * TM;
        }
        for (int k = off / TM; k < MTILES; k++) g_tile_group[k] = -1;
    }
    __syncthreads();

    for (int r = t; r < B_; r += blockDim.x) {
        int g = ei[r] * 2 + (hp[r] != 0);
        int pos = atomicAdd(&cur[g], 1);
        g_perm[pos] = r;
    }
}

// ---------------------------------------------------------------------------
// PTX helpers
// ---------------------------------------------------------------------------
__device__ __forceinline__ void ldsm_x4(uint32_t* r, uint32_t addr) {
    asm volatile("ldmatrix.sync.aligned.m8n8.x4.shared.b16 {%0,%1,%2,%3}, [%4];\n"
                 : "=r"(r[0]), "=r"(r[1]), "=r"(r[2]), "=r"(r[3]) : "r"(addr));
}
__device__ __forceinline__ void ldsm_x4_t(uint32_t* r, uint32_t addr) {
    asm volatile("ldmatrix.sync.aligned.m8n8.x4.trans.shared.b16 {%0,%1,%2,%3}, [%4];\n"
                 : "=r"(r[0]), "=r"(r[1]), "=r"(r[2]), "=r"(r[3]) : "r"(addr));
}
__device__ __forceinline__ void mma_fp16(float* c, const uint32_t* a,
                                         uint32_t b0, uint32_t b1) {
    asm volatile("mma.sync.aligned.m16n8k16.row.col.f32.f16.f16.f32 "
                 "{%0,%1,%2,%3}, {%4,%5,%6,%7}, {%8,%9}, {%0,%1,%2,%3};\n"
                 : "+f"(c[0]), "+f"(c[1]), "+f"(c[2]), "+f"(c[3])
                 : "r"(a[0]), "r"(a[1]), "r"(a[2]), "r"(a[3]), "r"(b0), "r"(b1));
}
__device__ __forceinline__ void split_fp16(float a, __half& hi, __half& lo) {
    hi = __float2half_rn(a);
    lo = __float2half_rn(a - __half2float(hi));
}
__device__ __forceinline__ void cp16(uint32_t d, const void* s) {
    asm volatile("cp.async.cg.shared.global [%0], [%1], 16;" :: "r"(d), "l"(s));
}
__device__ __forceinline__ void cp16z(uint32_t d, const void* s, uint32_t sz) {
    asm volatile("cp.async.cg.shared.global [%0], [%1], 16, %2;" :: "r"(d), "l"(s), "r"(sz));
}
#define CP_COMMIT() asm volatile("cp.async.commit_group;" ::: "memory")
#define CP_WAIT0()  asm volatile("cp.async.wait_group 0;" ::: "memory")

// ---------------------------------------------------------------------------
// Grouped GEMM, fp16 tensor cores. A = (ah + al) exact 2-term; B single fp16.
// Extra blockIdx.y rows (>= MTILES) convert next-stage weights fp32->fp16
// (DRAM pipe) concurrently with the GEMM CTAs (tensor pipe).
// ---------------------------------------------------------------------------
template<bool GELU, bool A16, bool OUT16>
__global__ __launch_bounds__(256, 2)
void gemm_tc(const float* __restrict__ Af,
             const __half* __restrict__ Ah, const __half* __restrict__ Al,
             int K, int N,
             const __half* __restrict__ Wp, const __half* __restrict__ Wq,
             const float* __restrict__ bp, const float* __restrict__ bq,
             float* __restrict__ OutF,
             __half* __restrict__ OutH, __half* __restrict__ OutL,
             const float* __restrict__ cvA, __half* __restrict__ cvAd,
             const float* __restrict__ cvB, __half* __restrict__ cvBd)
{
    int mt = blockIdx.y;
    int t = threadIdx.x;

    if (mt >= MTILES) {
        int nblk = (gridDim.y - MTILES) * gridDim.x;
        int cb   = (mt - MTILES) * gridDim.x + blockIdx.x;
        cvt_pair(cb, nblk, t, cvA, cvAd, cvB, cvBd, N4_BIG);
        return;
    }

    int g = g_tile_group[mt];
    if (g < 0) return;
    int e = g >> 1, sel = g & 1;
    const __half* W   = (sel ? Wq : Wp) + (size_t)e * K * N;
    const float* bias = (sel ? bq : bp) + (size_t)e * N;
    int n0 = blockIdx.x * TN;

    extern __shared__ __align__(16) __half dsm[];
    __half* As_hi = dsm + OFF_AS_HI;
    __half* As_lo = dsm + OFF_AS_LO;
    __half* Bs_hi = dsm + OFF_BS_HI;
    int* rows_s = (int*)(dsm + SMEM_H_TOT);

    if (t < TM) rows_s[t] = g_perm[mt * TM + t];
    __syncthreads();

    int lane = t & 31;
    int wid  = t >> 5;
    int wr = wid & 3;
    int wc = wid >> 2;

    uint32_t as_hi_u = (uint32_t)__cvta_generic_to_shared(As_hi);
    uint32_t as_lo_u = (uint32_t)__cvta_generic_to_shared(As_lo);
    uint32_t bs_hi_u = (uint32_t)__cvta_generic_to_shared(Bs_hi);

    // Loader mappings
    int ia_row = t >> 1;
    int ia_col = (t & 1) << 4;
    int rowA = rows_s[ia_row];
    uint32_t szA = (rowA >= 0) ? 16u : 0u;
    const __half* Ah_p = (rowA >= 0) ? Ah + (size_t)rowA * K + ia_col : Ah;
    const __half* Al_p = (rowA >= 0) ? Al + (size_t)rowA * K + ia_col : Al;
    const float*  Af_p = (rowA >= 0 && !A16) ? Af + (size_t)rowA * K + ia_col : (const float*)0;

    int ib_k = t >> 3;
    int ib_n = (t & 7) << 4;
    const __half* Bp = W + (size_t)ib_k * N + n0 + ib_n;

    uint32_t dA_off = (uint32_t)(ia_row * LDA_S + ia_col) * 2u;
    uint32_t dB_off = (uint32_t)(ib_k * LDB_S + ib_n) * 2u;

    // ldmatrix address components
    int a_row_off = lane & 15;
    int a_col_off = (lane >> 4) << 3;
    int bm = lane >> 3;
    int b_krow_off = ((bm & 1) << 3) + (lane & 7);
    int b_ncol_off = (bm >> 1) << 3;

    float acc[2][8][4];
    #pragma unroll
    for (int mi = 0; mi < 2; mi++)
        #pragma unroll
        for (int ni = 0; ni < 8; ni++)
            #pragma unroll
            for (int q = 0; q < 4; q++) acc[mi][ni][q] = 0.0f;

    auto issue_tile = [&](int buf, int k0) {
        uint32_t dh = as_hi_u + (uint32_t)(buf * A_PL) * 2u + dA_off;
        uint32_t dl = as_lo_u + (uint32_t)(buf * A_PL) * 2u + dA_off;
        cp16z(dh,      Ah_p + k0,     szA);
        cp16z(dh + 16, Ah_p + k0 + 8, szA);
        cp16z(dl,      Al_p + k0,     szA);
        cp16z(dl + 16, Al_p + k0 + 8, szA);
        uint32_t db = bs_hi_u + (uint32_t)(buf * B_PL) * 2u + dB_off;
        const __half* sB = Bp + (size_t)k0 * N;
        cp16(db,      sB);
        cp16(db + 16, sB + 8);
    };

    auto compute = [&](int buf) {
        uint32_t aBaseHi = as_hi_u + (uint32_t)(buf * A_PL) * 2u;
        uint32_t aBaseLo = as_lo_u + (uint32_t)(buf * A_PL) * 2u;
        uint32_t bBaseHi = bs_hi_u + (uint32_t)(buf * B_PL) * 2u;
        #pragma unroll
        for (int ks = 0; ks < 2; ks++) {
            uint32_t a_hi[2][4], a_lo[2][4], bfr[4];
            #pragma unroll
            for (int mi = 0; mi < 2; mi++) {
                int row = wr * 32 + mi * 16 + a_row_off;
                int cb  = ks * 16 + a_col_off;
                uint32_t off = (uint32_t)(row * LDA_S + cb) * 2u;
                ldsm_x4(a_hi[mi], aBaseHi + off);
                ldsm_x4(a_lo[mi], aBaseLo + off);
            }
            int krow = ks * 16 + b_krow_off;
            #pragma unroll
            for (int j = 0; j < 4; j++) {
                int ncol = wc * 64 + j * 16 + b_ncol_off;
                uint32_t off = (uint32_t)(krow * LDB_S + ncol) * 2u;
                ldsm_x4_t(bfr, bBaseHi + off);
                #pragma unroll
                for (int mi = 0; mi < 2; mi++) {
                    mma_fp16(acc[mi][2*j+0], a_hi[mi], bfr[0], bfr[1]);
                    mma_fp16(acc[mi][2*j+1], a_hi[mi], bfr[2], bfr[3]);
                    mma_fp16(acc[mi][2*j+0], a_lo[mi], bfr[0], bfr[1]);
                    mma_fp16(acc[mi][2*j+1], a_lo[mi], bfr[2], bfr[3]);
                }
            }
        }
    };

    int nk = K / TKK;

    if (A16) {
        issue_tile(0, 0); CP_COMMIT();
        CP_WAIT0(); __syncthreads();
        for (int it = 0; it < nk; it++) {
            int buf = it & 1;
            bool hn = (it + 1) < nk;
            if (hn) { issue_tile(buf ^ 1, (it + 1) * TKK); CP_COMMIT(); }
            compute(buf);
            if (hn) CP_WAIT0();
            __syncthreads();
        }
    } else {
        for (int it = 0; it < nk; it++) {
            int k0 = it * TKK;
            float va[16];
            #pragma unroll
            for (int i = 0; i < 4; i++) {
                float4 v = Af_p ? *(const float4*)(Af_p + k0 + i * 4)
                                : make_float4(0.f, 0.f, 0.f, 0.f);
                va[i*4+0] = v.x; va[i*4+1] = v.y; va[i*4+2] = v.z; va[i*4+3] = v.w;
            }
            uint32_t db = bs_hi_u + dB_off;
            const __half* sB = Bp + (size_t)k0 * N;
            cp16(db, sB); cp16(db + 16, sB + 8);
            CP_COMMIT();

            __half h[16], l[16];
            #pragma unroll
            for (int i = 0; i < 16; i++) split_fp16(va[i], h[i], l[i]);
            uint4* dh = (uint4*)&As_hi[ia_row * LDA_S + ia_col];
            uint4* dl = (uint4*)&As_lo[ia_row * LDA_S + ia_col];
            dh[0] = *(uint4*)&h[0]; dh[1] = *(uint4*)&h[8];
            dl[0] = *(uint4*)&l[0]; dl[1] = *(uint4*)&l[8];

            CP_WAIT0();
            __syncthreads();
            compute(0);
            __syncthreads();
        }
    }

    // ---- epilogue ----
    #pragma unroll
    for (int mi = 0; mi < 2; mi++) {
        #pragma unroll
        for (int half = 0; half < 2; half++) {
            int mrow = wr * 32 + mi * 16 + half * 8 + (lane >> 2);
            int r = rows_s[mrow];
            if (r < 0) continue;
            #pragma unroll
            for (int ni = 0; ni < 8; ni++) {
                int col = n0 + wc * 64 + ni * 8 + ((lane & 3) << 1);
                float v0 = acc[mi][ni][half * 2 + 0] + bias[col];
                float v1 = acc[mi][ni][half * 2 + 1] + bias[col + 1];
                if (GELU) {
                    v0 = 0.5f * v0 * (1.0f + erff(v0 * 0.7071067811865475f));
                    v1 = 0.5f * v1 * (1.0f + erff(v1 * 0.7071067811865475f));
                }
                if (OUT16) {
                    __half h0, l0, h1, l1;
                    split_fp16(v0, h0, l0);
                    split_fp16(v1, h1, l1);
                    __half hh[2] = {h0, h1};
                    __half ll[2] = {l0, l1};
                    *(uint32_t*)(OutH + (size_t)r * N + col) = *(uint32_t*)hh;
                    *(uint32_t*)(OutL + (size_t)r * N + col) = *(uint32_t*)ll;
                } else {
                    *(float2*)(OutF + (size_t)r * N + col) = make_float2(v0, v1);
                }
            }
        }
    }
}

// ---------------------------------------------------------------------------
// LayerNorm over D=1024; reads fp32 mid, writes pre-split fp16 planes.
// ---------------------------------------------------------------------------
__global__ __launch_bounds__(256)
void layernorm_k(const int* __restrict__ ei,
                 const float* __restrict__ ln_g, const float* __restrict__ ln_b,
                 const float* __restrict__ mid,
                 __half* __restrict__ outh, __half* __restrict__ outl)
{
    int r = blockIdx.x;
    int e = ei[r];
    const float* x = mid + (size_t)r * D_;
    int t = threadIdx.x;

    float v[4];
    float s = 0.f, ss = 0.f;
    #pragma unroll
    for (int i = 0; i < 4; i++) {
        v[i] = x[t + i * 256];
        s += v[i];
        ss += v[i] * v[i];
    }
    #pragma unroll
    for (int o = 16; o; o >>= 1) {
        s  += __shfl_xor_sync(0xffffffffu, s,  o);
        ss += __shfl_xor_sync(0xffffffffu, ss, o);
    }
    __shared__ float red[2][8];
    int w = t >> 5, l = t & 31;
    if (l == 0) { red[0][w] = s; red[1][w] = ss; }
    __syncthreads();
    float S = 0.f, SS = 0.f;
    #pragma unroll
    for (int i = 0; i < 8; i++) { S += red[0][i]; SS += red[1][i]; }

    float mu  = S * (1.0f / D_);
    float var = SS * (1.0f / D_) - mu * mu;
    float rstd = rsqrtf(var + LN_EPS);

    const float* gg = ln_g + (size_t)e * D_;
    const float* bb = ln_b + (size_t)e * D_;
    #pragma unroll
    for (int i = 0; i < 4; i++) {
        int c = t + i * 256;
        float y = (v[i] - mu) * rstd * gg[c] + bb[c];
        __half hi, lo;
        split_fp16(y, hi, lo);
        outh[(size_t)r * D_ + c] = hi;
        outl[(size_t)r * D_ + c] = lo;
    }
}

// ---------------------------------------------------------------------------
extern "C" void kernel_launch(void* const* d_in, const int* in_sizes, int n_in,
                              void* d_out, int out_size)
{
    const float* x   = (const float*)d_in[0];
    const int*   hp  = (const int*)d_in[1];
    const int*   ei  = (const int*)d_in[2];
    const float* pw1 = (const float*)d_in[3];
    const float* pb1 = (const float*)d_in[4];
    const float* pw2 = (const float*)d_in[5];
    const float* pb2 = (const float*)d_in[6];
    const float* qw1 = (const float*)d_in[7];
    const float* qb1 = (const float*)d_in[8];
    const float* qw2 = (const float*)d_in[9];
    const float* qb2 = (const float*)d_in[10];
    const float* lng = (const float*)d_in[11];
    const float* lnb = (const float*)d_in[12];
    const float* tw1 = (const float*)d_in[13];
    const float* tb1 = (const float*)d_in[14];
    const float* tw2 = (const float*)d_in[15];
    const float* tb2 = (const float*)d_in[16];
    float* out = (float*)d_out;

    __half *wh, *h1h, *h1l, *h2h, *h2l, *midh, *midl;
    float *mid;
    cudaGetSymbolAddress((void**)&wh,   g_wh);
    cudaGetSymbolAddress((void**)&h1h,  g_h1h);
    cudaGetSymbolAddress((void**)&h1l,  g_h1l);
    cudaGetSymbolAddress((void**)&h2h,  g_h2h);
    cudaGetSymbolAddress((void**)&h2l,  g_h2l);
    cudaGetSymbolAddress((void**)&midh, g_midh);
    cudaGetSymbolAddress((void**)&midl, g_midl);
    cudaGetSymbolAddress((void**)&mid,  g_mid);

    static bool attr_done = false;
    if (!attr_done) {
        cudaFuncSetAttribute(gemm_tc<true , false, true >, cudaFuncAttributeMaxDynamicSharedMemorySize, SMEM_BYTES);
        cudaFuncSetAttribute(gemm_tc<false, true , false>, cudaFuncAttributeMaxDynamicSharedMemorySize, SMEM_BYTES);
        cudaFuncSetAttribute(gemm_tc<true , true , true >, cudaFuncAttributeMaxDynamicSharedMemorySize, SMEM_BYTES);
        attr_done = true;
    }

    // Group build (block 0) + pw1/qw1 fp16 conversion (512 extra blocks)
    build_groups_cvt<<<1 + 512, 256>>>(hp, ei, pw1, wh + WH_PW1, qw1, wh + WH_QW1);

    // Stage 1: h1(planes) = gelu(x @ {p,q}w1 + b1)   K=64, fp32 A.
    // Extra 64 grid rows (x16 = 1024 CTAs) convert pw2/qw2 for stage 2.
    gemm_tc<true , false, true ><<<dim3(H_ / TN, MTILES + 64), 256, SMEM_BYTES>>>(
        x, (const __half*)0, (const __half*)0, S_, H_,
        wh + WH_PW1, wh + WH_QW1, pb1, qb1,
        (float*)0, h1h, h1l,
        pw2, wh + WH_PW2, qw2, wh + WH_QW2);
    // Stage 2: mid = h1 @ {p,q}w2 + b2               K=2048.
    // Extra 128 grid rows (x8 = 1024 CTAs) convert tw1/tw2 for stages 4/5.
    gemm_tc<false, true , false><<<dim3(D_ / TN, MTILES + 128), 256, SMEM_BYTES>>>(
        (const float*)0, h1h, h1l, H_, D_,
        wh + WH_PW2, wh + WH_QW2, pb2, qb2,
        mid, (__half*)0, (__half*)0,
        tw1, wh + WH_TW1, tw2, wh + WH_TW2);
    // Stage 3: layernorm -> mid planes
    layernorm_k<<<B_, 256>>>(ei, lng, lnb, mid, midh, midl);
    // Stage 4: h2(planes) = gelu(mid @ tw1 + tb1)    K=1024
    gemm_tc<true , true , true ><<<dim3(H_ / TN, MTILES), 256, SMEM_BYTES>>>(
        (const float*)0, midh, midl, D_, H_,
        wh + WH_TW1, wh + WH_TW1, tb1, tb1,
        (float*)0, h2h, h2l,
        (const float*)0, (__half*)0, (const float*)0, (__half*)0);
    // Stage 5: out = h2 @ tw2 + tb2                  K=2048
    gemm_tc<false, true , false><<<dim3(D_ / TN, MTILES), 256, SMEM_BYTES>>>(
        (const float*)0, h2h, h2l, H_, D_,
        wh + WH_TW2, wh + WH_TW2, tb2, tb2,
        out, (__half*)0, (__half*)0,
        (const float*)0, (__half*)0, (const float*)0, (__half*)0);
}

// round 14
// speedup vs baseline: 5.3746x; 1.5019x over previous
#include <cuda_runtime.h>
#include <cuda_fp16.h>
#include <math.h>
#include <stdint.h>
#include <cstdint>
#include <cstddef>

// Problem dims
#define E_ 8
#define S_ 64
#define H_ 2048
#define D_ 1024
#define B_ 8192
#define LN_EPS 1e-5f

// GEMM tiling
#define TM 128
#define TN 128
#define TKK 32
#define NGROUPS 16
#define P_MAX (B_ + NGROUPS * TM)       // 10240
#define MTILES (P_MAX / TM)             // 80

#define LDA_S 40                        // As row stride in fp16 (32 + 8 pad)
#define LDB_S 136                       // Bs row stride in fp16 (128 + 8 pad)

// Dynamic smem layout (elements): A hi(+lo, stage1 only) planes, B hi; 2 bufs.
#define A_PL (TM * LDA_S)               // 5120
#define B_PL (TKK * LDB_S)              // 4352
#define OFF_AS_HI 0
#define OFF_AS_LO (OFF_AS_HI + 2 * A_PL)
#define OFF_BS_HI (OFF_AS_LO + 2 * A_PL)
#define SMEM_H_TOT (OFF_BS_HI + 2 * B_PL)
#define SMEM_BYTES (SMEM_H_TOT * 2 + TM * 4)

// fp16 weight buffer offsets (in halfs)
#define WH_PW1 0
#define WH_QW1 (WH_PW1 + E_ * S_ * H_)
#define WH_PW2 (WH_QW1 + E_ * S_ * H_)
#define WH_QW2 (WH_PW2 + E_ * H_ * D_)
#define WH_TW1 (WH_QW2 + E_ * H_ * D_)
#define WH_TW2 (WH_TW1 + E_ * D_ * H_)
#define WH_TOT (WH_TW2 + E_ * H_ * D_)

#define N4_SMALL (E_ * S_ * H_ / 4)
#define N4_BIG   (E_ * H_ * D_ / 4)

// Scratch (device globals — no allocation allowed)
__device__ int    g_perm[P_MAX];
__device__ int    g_tile_group[MTILES];
__device__ __half g_wh[WH_TOT];
__device__ __half g_h1h[(size_t)B_ * H_];
__device__ __half g_h2h[(size_t)B_ * H_];
__device__ __half g_midh[(size_t)B_ * D_];
__device__ float  g_mid[(size_t)B_ * D_];

// ---------------------------------------------------------------------------
// Shared converter body
// ---------------------------------------------------------------------------
__device__ __forceinline__ void cvt_pair(int cb, int nblk, int tid,
                                         const float* srcA, __half* dstA,
                                         const float* srcB, __half* dstB, int n4)
{
    int half_blk = nblk >> 1;
    const float4* s;
    __half* d;
    int id;
    if (cb < half_blk) { s = (const float4*)srcA; d = dstA; id = cb; }
    else               { s = (const float4*)srcB; d = dstB; id = cb - half_blk; }
    int stride = half_blk * 256;
    for (int i = id * 256 + tid; i < n4; i += stride) {
        float4 v = s[i];
        __half h[4];
        h[0] = __float2half_rn(v.x); h[1] = __float2half_rn(v.y);
        h[2] = __float2half_rn(v.z); h[3] = __float2half_rn(v.w);
        *(uint2*)(d + (size_t)4 * i) = *(uint2*)h;
    }
}

// ---------------------------------------------------------------------------
// Group builder (block 0) + small-weight conversion (blocks 1..N).
// ---------------------------------------------------------------------------
__global__ void build_groups_cvt(const int* __restrict__ hp, const int* __restrict__ ei,
                                 const float* __restrict__ pw1, __half* __restrict__ pw1h,
                                 const float* __restrict__ qw1, __half* __restrict__ qw1h)
{
    int t = threadIdx.x;
    if (blockIdx.x > 0) {
        cvt_pair(blockIdx.x - 1, gridDim.x - 1, t, pw1, pw1h, qw1, qw1h, N4_SMALL);
        return;
    }

    __shared__ int cnt[NGROUPS];
    __shared__ int cur[NGROUPS];
    if (t < NGROUPS) cnt[t] = 0;
    __syncthreads();

    for (int r = t; r < B_; r += blockDim.x) {
        int g = ei[r] * 2 + (hp[r] != 0);
        atomicAdd(&cnt[g], 1);
    }
    for (int i = t; i < P_MAX; i += blockDim.x) g_perm[i] = -1;
    __syncthreads();

    if (t == 0) {
        int off = 0;
        for (int g = 0; g < NGROUPS; g++) {
            cur[g] = off;
            int ntile = (cnt[g] + TM - 1) / TM;
            int t0 = off / TM;
            for (int k = 0; k < ntile; k++) g_tile_group[t0 + k] = g;
            off += ntile * TM;
        }
        for (int k = off / TM; k < MTILES; k++) g_tile_group[k] = -1;
    }
    __syncthreads();

    for (int r = t; r < B_; r += blockDim.x) {
        int g = ei[r] * 2 + (hp[r] != 0);
        int pos = atomicAdd(&cur[g], 1);
        g_perm[pos] = r;
    }
}

// ---------------------------------------------------------------------------
// PTX helpers
// ---------------------------------------------------------------------------
__device__ __forceinline__ void ldsm_x4(uint32_t* r, uint32_t addr) {
    asm volatile("ldmatrix.sync.aligned.m8n8.x4.shared.b16 {%0,%1,%2,%3}, [%4];\n"
                 : "=r"(r[0]), "=r"(r[1]), "=r"(r[2]), "=r"(r[3]) : "r"(addr));
}
__device__ __forceinline__ void ldsm_x4_t(uint32_t* r, uint32_t addr) {
    asm volatile("ldmatrix.sync.aligned.m8n8.x4.trans.shared.b16 {%0,%1,%2,%3}, [%4];\n"
                 : "=r"(r[0]), "=r"(r[1]), "=r"(r[2]), "=r"(r[3]) : "r"(addr));
}
__device__ __forceinline__ void mma_fp16(float* c, const uint32_t* a,
                                         uint32_t b0, uint32_t b1) {
    asm volatile("mma.sync.aligned.m16n8k16.row.col.f32.f16.f16.f32 "
                 "{%0,%1,%2,%3}, {%4,%5,%6,%7}, {%8,%9}, {%0,%1,%2,%3};\n"
                 : "+f"(c[0]), "+f"(c[1]), "+f"(c[2]), "+f"(c[3])
                 : "r"(a[0]), "r"(a[1]), "r"(a[2]), "r"(a[3]), "r"(b0), "r"(b1));
}
__device__ __forceinline__ void split_fp16(float a, __half& hi, __half& lo) {
    hi = __float2half_rn(a);
    lo = __float2half_rn(a - __half2float(hi));
}
__device__ __forceinline__ void cp16(uint32_t d, const void* s) {
    asm volatile("cp.async.cg.shared.global [%0], [%1], 16;" :: "r"(d), "l"(s));
}
__device__ __forceinline__ void cp16z(uint32_t d, const void* s, uint32_t sz) {
    asm volatile("cp.async.cg.shared.global [%0], [%1], 16, %2;" :: "r"(d), "l"(s), "r"(sz));
}
#define CP_COMMIT() asm volatile("cp.async.commit_group;" ::: "memory")
#define CP_WAIT0()  asm volatile("cp.async.wait_group 0;" ::: "memory")

// ---------------------------------------------------------------------------
// Grouped GEMM, fp16 tensor cores.
// A16 path: A single fp16 plane via cp.async (1 MMA term).
// !A16 path (stage 1): fp32 A, exact 2-term split (hh + lh).
// Extra blockIdx.y rows (>= MTILES) convert next-stage weights concurrently.
// ---------------------------------------------------------------------------
template<bool GELU, bool A16, bool OUT16>
__global__ __launch_bounds__(256, 2)
void gemm_tc(const float* __restrict__ Af,
             const __half* __restrict__ Ah,
             int K, int N,
             const __half* __restrict__ Wp, const __half* __restrict__ Wq,
             const float* __restrict__ bp, const float* __restrict__ bq,
             float* __restrict__ OutF, __half* __restrict__ OutH,
             const float* __restrict__ cvA, __half* __restrict__ cvAd,
             const float* __restrict__ cvB, __half* __restrict__ cvBd)
{
    int mt = blockIdx.y;
    int t = threadIdx.x;

    if (mt >= MTILES) {
        int nblk = (gridDim.y - MTILES) * gridDim.x;
        int cb   = (mt - MTILES) * gridDim.x + blockIdx.x;
        cvt_pair(cb, nblk, t, cvA, cvAd, cvB, cvBd, N4_BIG);
        return;
    }

    int g = g_tile_group[mt];
    if (g < 0) return;
    int e = g >> 1, sel = g & 1;
    const __half* W   = (sel ? Wq : Wp) + (size_t)e * K * N;
    const float* bias = (sel ? bq : bp) + (size_t)e * N;
    int n0 = blockIdx.x * TN;

    extern __shared__ __align__(16) __half dsm[];
    __half* As_hi = dsm + OFF_AS_HI;
    __half* As_lo = dsm + OFF_AS_LO;
    __half* Bs_hi = dsm + OFF_BS_HI;
    int* rows_s = (int*)(dsm + SMEM_H_TOT);

    if (t < TM) rows_s[t] = g_perm[mt * TM + t];
    __syncthreads();

    int lane = t & 31;
    int wid  = t >> 5;
    int wr = wid & 3;
    int wc = wid >> 2;

    uint32_t as_hi_u = (uint32_t)__cvta_generic_to_shared(As_hi);
    uint32_t as_lo_u = (uint32_t)__cvta_generic_to_shared(As_lo);
    uint32_t bs_hi_u = (uint32_t)__cvta_generic_to_shared(Bs_hi);

    // Loader mappings
    int ia_row = t >> 1;
    int ia_col = (t & 1) << 4;
    int rowA = rows_s[ia_row];
    uint32_t szA = (rowA >= 0) ? 16u : 0u;
    const __half* Ah_p = (rowA >= 0) ? Ah + (size_t)rowA * K + ia_col : Ah;
    const float*  Af_p = (rowA >= 0 && !A16) ? Af + (size_t)rowA * K + ia_col : (const float*)0;

    int ib_k = t >> 3;
    int ib_n = (t & 7) << 4;
    const __half* Bp = W + (size_t)ib_k * N + n0 + ib_n;

    uint32_t dA_off = (uint32_t)(ia_row * LDA_S + ia_col) * 2u;
    uint32_t dB_off = (uint32_t)(ib_k * LDB_S + ib_n) * 2u;

    // ldmatrix address components
    int a_row_off = lane & 15;
    int a_col_off = (lane >> 4) << 3;
    int bm = lane >> 3;
    int b_krow_off = ((bm & 1) << 3) + (lane & 7);
    int b_ncol_off = (bm >> 1) << 3;

    float acc[2][8][4];
    #pragma unroll
    for (int mi = 0; mi < 2; mi++)
        #pragma unroll
        for (int ni = 0; ni < 8; ni++)
            #pragma unroll
            for (int q = 0; q < 4; q++) acc[mi][ni][q] = 0.0f;

    auto issue_tile = [&](int buf, int k0) {
        uint32_t dh = as_hi_u + (uint32_t)(buf * A_PL) * 2u + dA_off;
        cp16z(dh,      Ah_p + k0,     szA);
        cp16z(dh + 16, Ah_p + k0 + 8, szA);
        uint32_t db = bs_hi_u + (uint32_t)(buf * B_PL) * 2u + dB_off;
        const __half* sB = Bp + (size_t)k0 * N;
        cp16(db,      sB);
        cp16(db + 16, sB + 8);
    };

    auto compute = [&](int buf) {
        uint32_t aBaseHi = as_hi_u + (uint32_t)(buf * A_PL) * 2u;
        uint32_t aBaseLo = as_lo_u + (uint32_t)(buf * A_PL) * 2u;
        uint32_t bBaseHi = bs_hi_u + (uint32_t)(buf * B_PL) * 2u;
        #pragma unroll
        for (int ks = 0; ks < 2; ks++) {
            uint32_t a_hi[2][4], a_lo[2][4], bfr[4];
            #pragma unroll
            for (int mi = 0; mi < 2; mi++) {
                int row = wr * 32 + mi * 16 + a_row_off;
                int cb  = ks * 16 + a_col_off;
                uint32_t off = (uint32_t)(row * LDA_S + cb) * 2u;
                ldsm_x4(a_hi[mi], aBaseHi + off);
                if (!A16) ldsm_x4(a_lo[mi], aBaseLo + off);
            }
            int krow = ks * 16 + b_krow_off;
            #pragma unroll
            for (int j = 0; j < 4; j++) {
                int ncol = wc * 64 + j * 16 + b_ncol_off;
                uint32_t off = (uint32_t)(krow * LDB_S + ncol) * 2u;
                ldsm_x4_t(bfr, bBaseHi + off);
                #pragma unroll
                for (int mi = 0; mi < 2; mi++) {
                    mma_fp16(acc[mi][2*j+0], a_hi[mi], bfr[0], bfr[1]);
                    mma_fp16(acc[mi][2*j+1], a_hi[mi], bfr[2], bfr[3]);
                    if (!A16) {
                        mma_fp16(acc[mi][2*j+0], a_lo[mi], bfr[0], bfr[1]);
                        mma_fp16(acc[mi][2*j+1], a_lo[mi], bfr[2], bfr[3]);
                    }
                }
            }
        }
    };

    int nk = K / TKK;

    if (A16) {
        issue_tile(0, 0); CP_COMMIT();
        CP_WAIT0(); __syncthreads();
        for (int it = 0; it < nk; it++) {
            int buf = it & 1;
            bool hn = (it + 1) < nk;
            if (hn) { issue_tile(buf ^ 1, (it + 1) * TKK); CP_COMMIT(); }
            compute(buf);
            if (hn) CP_WAIT0();
            __syncthreads();
        }
    } else {
        for (int it = 0; it < nk; it++) {
            int k0 = it * TKK;
            float va[16];
            #pragma unroll
            for (int i = 0; i < 4; i++) {
                float4 v = Af_p ? *(const float4*)(Af_p + k0 + i * 4)
                                : make_float4(0.f, 0.f, 0.f, 0.f);
                va[i*4+0] = v.x; va[i*4+1] = v.y; va[i*4+2] = v.z; va[i*4+3] = v.w;
            }
            uint32_t db = bs_hi_u + dB_off;
            const __half* sB = Bp + (size_t)k0 * N;
            cp16(db, sB); cp16(db + 16, sB + 8);
            CP_COMMIT();

            __half h[16], l[16];
            #pragma unroll
            for (int i = 0; i < 16; i++) split_fp16(va[i], h[i], l[i]);
            uint4* dh = (uint4*)&As_hi[ia_row * LDA_S + ia_col];
            uint4* dl = (uint4*)&As_lo[ia_row * LDA_S + ia_col];
            dh[0] = *(uint4*)&h[0]; dh[1] = *(uint4*)&h[8];
            dl[0] = *(uint4*)&l[0]; dl[1] = *(uint4*)&l[8];

            CP_WAIT0();
            __syncthreads();
            compute(0);
            __syncthreads();
        }
    }

    // ---- epilogue ----
    #pragma unroll
    for (int mi = 0; mi < 2; mi++) {
        #pragma unroll
        for (int half = 0; half < 2; half++) {
            int mrow = wr * 32 + mi * 16 + half * 8 + (lane >> 2);
            int r = rows_s[mrow];
            if (r < 0) continue;
            #pragma unroll
            for (int ni = 0; ni < 8; ni++) {
                int col = n0 + wc * 64 + ni * 8 + ((lane & 3) << 1);
                float v0 = acc[mi][ni][half * 2 + 0] + bias[col];
                float v1 = acc[mi][ni][half * 2 + 1] + bias[col + 1];
                if (GELU) {
                    v0 = 0.5f * v0 * (1.0f + erff(v0 * 0.7071067811865475f));
                    v1 = 0.5f * v1 * (1.0f + erff(v1 * 0.7071067811865475f));
                }
                if (OUT16) {
                    __half hh[2] = {__float2half_rn(v0), __float2half_rn(v1)};
                    *(uint32_t*)(OutH + (size_t)r * N + col) = *(uint32_t*)hh;
                } else {
                    *(float2*)(OutF + (size_t)r * N + col) = make_float2(v0, v1);
                }
            }
        }
    }
}

// ---------------------------------------------------------------------------
// LayerNorm over D=1024; reads fp32 mid, writes fp16 plane.
// ---------------------------------------------------------------------------
__global__ __launch_bounds__(256)
void layernorm_k(const int* __restrict__ ei,
                 const float* __restrict__ ln_g, const float* __restrict__ ln_b,
                 const float* __restrict__ mid,
                 __half* __restrict__ outh)
{
    int r = blockIdx.x;
    int e = ei[r];
    const float* x = mid + (size_t)r * D_;
    int t = threadIdx.x;

    float v[4];
    float s = 0.f, ss = 0.f;
    #pragma unroll
    for (int i = 0; i < 4; i++) {
        v[i] = x[t + i * 256];
        s += v[i];
        ss += v[i] * v[i];
    }
    #pragma unroll
    for (int o = 16; o; o >>= 1) {
        s  += __shfl_xor_sync(0xffffffffu, s,  o);
        ss += __shfl_xor_sync(0xffffffffu, ss, o);
    }
    __shared__ float red[2][8];
    int w = t >> 5, l = t & 31;
    if (l == 0) { red[0][w] = s; red[1][w] = ss; }
    __syncthreads();
    float S = 0.f, SS = 0.f;
    #pragma unroll
    for (int i = 0; i < 8; i++) { S += red[0][i]; SS += red[1][i]; }

    float mu  = S * (1.0f / D_);
    float var = SS * (1.0f / D_) - mu * mu;
    float rstd = rsqrtf(var + LN_EPS);

    const float* gg = ln_g + (size_t)e * D_;
    const float* bb = ln_b + (size_t)e * D_;
    #pragma unroll
    for (int i = 0; i < 4; i++) {
        int c = t + i * 256;
        float y = (v[i] - mu) * rstd * gg[c] + bb[c];
        outh[(size_t)r * D_ + c] = __float2half_rn(y);
    }
}

// ---------------------------------------------------------------------------
extern "C" void kernel_launch(void* const* d_in, const int* in_sizes, int n_in,
                              void* d_out, int out_size)
{
    const float* x   = (const float*)d_in[0];
    const int*   hp  = (const int*)d_in[1];
    const int*   ei  = (const int*)d_in[2];
    const float* pw1 = (const float*)d_in[3];
    const float* pb1 = (const float*)d_in[4];
    const float* pw2 = (const float*)d_in[5];
    const float* pb2 = (const float*)d_in[6];
    const float* qw1 = (const float*)d_in[7];
    const float* qb1 = (const float*)d_in[8];
    const float* qw2 = (const float*)d_in[9];
    const float* qb2 = (const float*)d_in[10];
    const float* lng = (const float*)d_in[11];
    const float* lnb = (const float*)d_in[12];
    const float* tw1 = (const float*)d_in[13];
    const float* tb1 = (const float*)d_in[14];
    const float* tw2 = (const float*)d_in[15];
    const float* tb2 = (const float*)d_in[16];
    float* out = (float*)d_out;

    __half *wh, *h1h, *h2h, *midh;
    float *mid;
    cudaGetSymbolAddress((void**)&wh,   g_wh);
    cudaGetSymbolAddress((void**)&h1h,  g_h1h);
    cudaGetSymbolAddress((void**)&h2h,  g_h2h);
    cudaGetSymbolAddress((void**)&midh, g_midh);
    cudaGetSymbolAddress((void**)&mid,  g_mid);

    static bool attr_done = false;
    if (!attr_done) {
        cudaFuncSetAttribute(gemm_tc<true , false, true >, cudaFuncAttributeMaxDynamicSharedMemorySize, SMEM_BYTES);
        cudaFuncSetAttribute(gemm_tc<false, true , false>, cudaFuncAttributeMaxDynamicSharedMemorySize, SMEM_BYTES);
        cudaFuncSetAttribute(gemm_tc<true , true , true >, cudaFuncAttributeMaxDynamicSharedMemorySize, SMEM_BYTES);
        attr_done = true;
    }

    // Group build (block 0) + pw1/qw1 fp16 conversion (512 extra blocks)
    build_groups_cvt<<<1 + 512, 256>>>(hp, ei, pw1, wh + WH_PW1, qw1, wh + WH_QW1);

    // Stage 1: h1(fp16) = gelu(x @ {p,q}w1 + b1)   K=64, fp32 A, 2-term exact.
    // Extra 64 grid rows convert pw2/qw2 for stage 2.
    gemm_tc<true , false, true ><<<dim3(H_ / TN, MTILES + 64), 256, SMEM_BYTES>>>(
        x, (const __half*)0, S_, H_,
        wh + WH_PW1, wh + WH_QW1, pb1, qb1,
        (float*)0, h1h,
        pw2, wh + WH_PW2, qw2, wh + WH_QW2);
    // Stage 2: mid = h1 @ {p,q}w2 + b2             K=2048, single-fp16 A.
    // Extra 128 grid rows convert tw1/tw2 for stages 4/5.
    gemm_tc<false, true , false><<<dim3(D_ / TN, MTILES + 128), 256, SMEM_BYTES>>>(
        (const float*)0, h1h, H_, D_,
        wh + WH_PW2, wh + WH_QW2, pb2, qb2,
        mid, (__half*)0,
        tw1, wh + WH_TW1, tw2, wh + WH_TW2);
    // Stage 3: layernorm -> fp16 plane
    layernorm_k<<<B_, 256>>>(ei, lng, lnb, mid, midh);
    // Stage 4: h2(fp16) = gelu(mid @ tw1 + tb1)    K=1024, single-fp16 A.
    gemm_tc<true , true , true ><<<dim3(H_ / TN, MTILES), 256, SMEM_BYTES>>>(
        (const float*)0, midh, D_, H_,
        wh + WH_TW1, wh + WH_TW1, tb1, tb1,
        (float*)0, h2h,
        (const float*)0, (__half*)0, (const float*)0, (__half*)0);
    // Stage 5: out = h2 @ tw2 + tb2                K=2048, single-fp16 A.
    gemm_tc<false, true , false><<<dim3(D_ / TN, MTILES), 256, SMEM_BYTES>>>(
        (const float*)0, h2h, H_, D_,
        wh + WH_TW2, wh + WH_TW2, tb2, tb2,
        out, (__half*)0,
        (const float*)0, (__half*)0, (const float*)0, (__half*)0);
}

// round 16
// speedup vs baseline: 5.8050x; 1.0801x over previous
#include <cuda_runtime.h>
#include <cuda_fp16.h>
#include <math.h>
#include <stdint.h>
#include <cstdint>
#include <cstddef>

// Problem dims
#define E_ 8
#define S_ 64
#define H_ 2048
#define D_ 1024
#define B_ 8192
#define LN_EPS 1e-5f

// GEMM tiling
#define TM 128
#define TN 128
#define TKK 32
#define NGROUPS 16
#define P_MAX (B_ + NGROUPS * TM)       // 10240
#define MTILES (P_MAX / TM)             // 80

#define LDA_S 40                        // As row stride in fp16 (32 + 8 pad)
#define LDB_S 136                       // Bs row stride in fp16 (128 + 8 pad)

#define A_PL (TM * LDA_S)               // 5120 halfs
#define B_PL (TKK * LDB_S)              // 4352 halfs
#define NSTAGE 4                        // cp.async pipeline depth (A16 path)
#define STG_PL (A_PL + B_PL)            // 9472 halfs per stage
#define SMEM_H_TOT (NSTAGE * STG_PL)    // 37888 halfs (covers !A16 layout too)
#define SMEM_BYTES (SMEM_H_TOT * 2 + TM * 4)   // 76288 B; occ 2 = 152.6 KB

// fp16 weight buffer offsets (in halfs)
#define WH_PW1 0
#define WH_QW1 (WH_PW1 + E_ * S_ * H_)
#define WH_PW2 (WH_QW1 + E_ * S_ * H_)
#define WH_QW2 (WH_PW2 + E_ * H_ * D_)
#define WH_TW1 (WH_QW2 + E_ * H_ * D_)
#define WH_TW2 (WH_TW1 + E_ * D_ * H_)
#define WH_TOT (WH_TW2 + E_ * H_ * D_)

#define N4_SMALL (E_ * S_ * H_ / 4)
#define N4_BIG   (E_ * H_ * D_ / 4)

// Scratch (device globals — no allocation allowed)
__device__ int    g_perm[P_MAX];
__device__ int    g_tile_group[MTILES];
__device__ __half g_wh[WH_TOT];
__device__ __half g_h1h[(size_t)B_ * H_];
__device__ __half g_h2h[(size_t)B_ * H_];
__device__ __half g_midh[(size_t)B_ * D_];
__device__ float  g_mid[(size_t)B_ * D_];

// ---------------------------------------------------------------------------
// Shared converter body
// ---------------------------------------------------------------------------
__device__ __forceinline__ void cvt_pair(int cb, int nblk, int tid,
                                         const float* srcA, __half* dstA,
                                         const float* srcB, __half* dstB, int n4)
{
    int half_blk = nblk >> 1;
    const float4* s;
    __half* d;
    int id;
    if (cb < half_blk) { s = (const float4*)srcA; d = dstA; id = cb; }
    else               { s = (const float4*)srcB; d = dstB; id = cb - half_blk; }
    int stride = half_blk * 256;
    for (int i = id * 256 + tid; i < n4; i += stride) {
        float4 v = s[i];
        __half h[4];
        h[0] = __float2half_rn(v.x); h[1] = __float2half_rn(v.y);
        h[2] = __float2half_rn(v.z); h[3] = __float2half_rn(v.w);
        *(uint2*)(d + (size_t)4 * i) = *(uint2*)h;
    }
}

// ---------------------------------------------------------------------------
// Group builder (block 0) + small-weight conversion (blocks 1..N).
// ---------------------------------------------------------------------------
__global__ void build_groups_cvt(const int* __restrict__ hp, const int* __restrict__ ei,
                                 const float* __restrict__ pw1, __half* __restrict__ pw1h,
                                 const float* __restrict__ qw1, __half* __restrict__ qw1h)
{
    int t = threadIdx.x;
    if (blockIdx.x > 0) {
        cvt_pair(blockIdx.x - 1, gridDim.x - 1, t, pw1, pw1h, qw1, qw1h, N4_SMALL);
        return;
    }

    __shared__ int cnt[NGROUPS];
    __shared__ int cur[NGROUPS];
    if (t < NGROUPS) cnt[t] = 0;
    __syncthreads();

    for (int r = t; r < B_; r += blockDim.x) {
        int g = ei[r] * 2 + (hp[r] != 0);
        atomicAdd(&cnt[g], 1);
    }
    for (int i = t; i < P_MAX; i += blockDim.x) g_perm[i] = -1;
    __syncthreads();

    if (t == 0) {
        int off = 0;
        for (int g = 0; g < NGROUPS; g++) {
            cur[g] = off;
            int ntile = (cnt[g] + TM - 1) / TM;
            int t0 = off / TM;
            for (int k = 0; k < ntile; k++) g_tile_group[t0 + k] = g;
            off += ntile * TM;
        }
        for (int k = off / TM; k < MTILES; k++) g_tile_group[k] = -1;
    }
    __syncthreads();

    for (int r = t; r < B_; r += blockDim.x) {
        int g = ei[r] * 2 + (hp[r] != 0);
        int pos = atomicAdd(&cur[g], 1);
        g_perm[pos] = r;
    }
}

// ---------------------------------------------------------------------------
// PTX helpers
// ---------------------------------------------------------------------------
__device__ __forceinline__ void ldsm_x4(uint32_t* r, uint32_t addr) {
    asm volatile("ldmatrix.sync.aligned.m8n8.x4.shared.b16 {%0,%1,%2,%3}, [%4];\n"
                 : "=r"(r[0]), "=r"(r[1]), "=r"(r[2]), "=r"(r[3]) : "r"(addr));
}
__device__ __forceinline__ void ldsm_x4_t(uint32_t* r, uint32_t addr) {
    asm volatile("ldmatrix.sync.aligned.m8n8.x4.trans.shared.b16 {%0,%1,%2,%3}, [%4];\n"
                 : "=r"(r[0]), "=r"(r[1]), "=r"(r[2]), "=r"(r[3]) : "r"(addr));
}
__device__ __forceinline__ void mma_fp16(float* c, const uint32_t* a,
                                         uint32_t b0, uint32_t b1) {
    asm volatile("mma.sync.aligned.m16n8k16.row.col.f32.f16.f16.f32 "
                 "{%0,%1,%2,%3}, {%4,%5,%6,%7}, {%8,%9}, {%0,%1,%2,%3};\n"
                 : "+f"(c[0]), "+f"(c[1]), "+f"(c[2]), "+f"(c[3])
                 : "r"(a[0]), "r"(a[1]), "r"(a[2]), "r"(a[3]), "r"(b0), "r"(b1));
}
__device__ __forceinline__ void split_fp16(float a, __half& hi, __half& lo) {
    hi = __float2half_rn(a);
    lo = __float2half_rn(a - __half2float(hi));
}
__device__ __forceinline__ void cp16(uint32_t d, const void* s) {
    asm volatile("cp.async.cg.shared.global [%0], [%1], 16;" :: "r"(d), "l"(s));
}
__device__ __forceinline__ void cp16z(uint32_t d, const void* s, uint32_t sz) {
    asm volatile("cp.async.cg.shared.global [%0], [%1], 16, %2;" :: "r"(d), "l"(s), "r"(sz));
}
#define CP_COMMIT() asm volatile("cp.async.commit_group;" ::: "memory")
#define CP_WAIT0()  asm volatile("cp.async.wait_group 0;" ::: "memory")
#define CP_WAIT2()  asm volatile("cp.async.wait_group 2;" ::: "memory")

// ---------------------------------------------------------------------------
// Grouped GEMM, fp16 tensor cores.
// A16: single-fp16 A, 4-stage cp.async pipeline (requires nk >= NSTAGE).
// !A16 (stage 1 only, nk=2): fp32 A, exact 2-term split, single buffer.
// Extra blockIdx.y rows (>= MTILES) convert next-stage weights concurrently.
// ---------------------------------------------------------------------------
template<bool GELU, bool A16, bool OUT16>
__global__ __launch_bounds__(256, 2)
void gemm_tc(const float* __restrict__ Af,
             const __half* __restrict__ Ah,
             int K, int N,
             const __half* __restrict__ Wp, const __half* __restrict__ Wq,
             const float* __restrict__ bp, const float* __restrict__ bq,
             float* __restrict__ OutF, __half* __restrict__ OutH,
             const float* __restrict__ cvA, __half* __restrict__ cvAd,
             const float* __restrict__ cvB, __half* __restrict__ cvBd)
{
    int mt = blockIdx.y;
    int t = threadIdx.x;

    if (mt >= MTILES) {
        int nblk = (gridDim.y - MTILES) * gridDim.x;
        int cb   = (mt - MTILES) * gridDim.x + blockIdx.x;
        cvt_pair(cb, nblk, t, cvA, cvAd, cvB, cvBd, N4_BIG);
        return;
    }

    int g = g_tile_group[mt];
    if (g < 0) return;
    int e = g >> 1, sel = g & 1;
    const __half* W   = (sel ? Wq : Wp) + (size_t)e * K * N;
    const float* bias = (sel ? bq : bp) + (size_t)e * N;
    int n0 = blockIdx.x * TN;

    extern __shared__ __align__(16) __half dsm[];
    int* rows_s = (int*)(dsm + SMEM_H_TOT);

    if (t < TM) rows_s[t] = g_perm[mt * TM + t];
    __syncthreads();

    int lane = t & 31;
    int wid  = t >> 5;
    int wr = wid & 3;
    int wc = wid >> 2;

    uint32_t smem_u = (uint32_t)__cvta_generic_to_shared(dsm);

    // Loader mappings
    int ia_row = t >> 1;
    int ia_col = (t & 1) << 4;
    int rowA = rows_s[ia_row];
    uint32_t szA = (rowA >= 0) ? 16u : 0u;
    const __half* Ah_p = (rowA >= 0) ? Ah + (size_t)rowA * K + ia_col : Ah;
    const float*  Af_p = (rowA >= 0 && !A16) ? Af + (size_t)rowA * K + ia_col : (const float*)0;

    int ib_k = t >> 3;
    int ib_n = (t & 7) << 4;
    const __half* Bp = W + (size_t)ib_k * N + n0 + ib_n;

    uint32_t dA_off = (uint32_t)(ia_row * LDA_S + ia_col) * 2u;
    uint32_t dB_off = (uint32_t)(ib_k * LDB_S + ib_n) * 2u;

    // ldmatrix address components
    int a_row_off = lane & 15;
    int a_col_off = (lane >> 4) << 3;
    int bm = lane >> 3;
    int b_krow_off = ((bm & 1) << 3) + (lane & 7);
    int b_ncol_off = (bm >> 1) << 3;

    float acc[2][8][4];
    #pragma unroll
    for (int mi = 0; mi < 2; mi++)
        #pragma unroll
        for (int ni = 0; ni < 8; ni++)
            #pragma unroll
            for (int q = 0; q < 4; q++) acc[mi][ni][q] = 0.0f;

    // A16 stage layout: stage s -> A_hi at s*STG_PL, B at s*STG_PL + A_PL
    auto issue_tile = [&](int stg, int k0) {
        uint32_t base = smem_u + (uint32_t)(stg * STG_PL) * 2u;
        uint32_t dh = base + dA_off;
        cp16z(dh,      Ah_p + k0,     szA);
        cp16z(dh + 16, Ah_p + k0 + 8, szA);
        uint32_t db = base + (uint32_t)A_PL * 2u + dB_off;
        const __half* sB = Bp + (size_t)k0 * N;
        cp16(db,      sB);
        cp16(db + 16, sB + 8);
    };

    // compute on explicit bases; aLo only used when !A16
    auto compute = [&](uint32_t aBaseHi, uint32_t aBaseLo, uint32_t bBase) {
        #pragma unroll
        for (int ks = 0; ks < 2; ks++) {
            uint32_t a_hi[2][4], a_lo[2][4], bfr[4];
            #pragma unroll
            for (int mi = 0; mi < 2; mi++) {
                int row = wr * 32 + mi * 16 + a_row_off;
                int cb  = ks * 16 + a_col_off;
                uint32_t off = (uint32_t)(row * LDA_S + cb) * 2u;
                ldsm_x4(a_hi[mi], aBaseHi + off);
                if (!A16) ldsm_x4(a_lo[mi], aBaseLo + off);
            }
            int krow = ks * 16 + b_krow_off;
            #pragma unroll
            for (int j = 0; j < 4; j++) {
                int ncol = wc * 64 + j * 16 + b_ncol_off;
                uint32_t off = (uint32_t)(krow * LDB_S + ncol) * 2u;
                ldsm_x4_t(bfr, bBase + off);
                #pragma unroll
                for (int mi = 0; mi < 2; mi++) {
                    mma_fp16(acc[mi][2*j+0], a_hi[mi], bfr[0], bfr[1]);
                    mma_fp16(acc[mi][2*j+1], a_hi[mi], bfr[2], bfr[3]);
                    if (!A16) {
                        mma_fp16(acc[mi][2*j+0], a_lo[mi], bfr[0], bfr[1]);
                        mma_fp16(acc[mi][2*j+1], a_lo[mi], bfr[2], bfr[3]);
                    }
                }
            }
        }
    };

    int nk = K / TKK;

    if (A16) {
        // 4-stage pipeline; valid because nk >= NSTAGE for all A16 stages.
        #pragma unroll
        for (int s = 0; s < NSTAGE - 1; s++) {
            issue_tile(s, s * TKK);
            CP_COMMIT();
        }
        for (int it = 0; it < nk; it++) {
            CP_WAIT2();            // oldest pending group (stage it) arrived
            __syncthreads();       // all threads' copies visible; buf (it-1)%4 free
            int nx = it + NSTAGE - 1;
            if (nx < nk) issue_tile(nx & (NSTAGE - 1), nx * TKK);
            CP_COMMIT();           // always commit to keep group counts aligned
            uint32_t base = smem_u + (uint32_t)((it & (NSTAGE - 1)) * STG_PL) * 2u;
            compute(base, 0u, base + (uint32_t)A_PL * 2u);
        }
    } else {
        // stage 1 (nk=2): single buffer, fp32 A with exact 2-term split.
        uint32_t aHi = smem_u;
        uint32_t aLo = smem_u + (uint32_t)A_PL * 2u;
        uint32_t bB  = smem_u + (uint32_t)(2 * A_PL) * 2u;
        for (int it = 0; it < nk; it++) {
            int k0 = it * TKK;
            float va[16];
            #pragma unroll
            for (int i = 0; i < 4; i++) {
                float4 v = Af_p ? *(const float4*)(Af_p + k0 + i * 4)
                                : make_float4(0.f, 0.f, 0.f, 0.f);
                va[i*4+0] = v.x; va[i*4+1] = v.y; va[i*4+2] = v.z; va[i*4+3] = v.w;
            }
            uint32_t db = bB + dB_off;
            const __half* sB = Bp + (size_t)k0 * N;
            cp16(db, sB); cp16(db + 16, sB + 8);
            CP_COMMIT();

            __half h[16], l[16];
            #pragma unroll
            for (int i = 0; i < 16; i++) split_fp16(va[i], h[i], l[i]);
            uint4* dh = (uint4*)((char*)dsm + aHi - smem_u + dA_off);
            uint4* dl = (uint4*)((char*)dsm + aLo - smem_u + dA_off);
            dh[0] = *(uint4*)&h[0]; dh[1] = *(uint4*)&h[8];
            dl[0] = *(uint4*)&l[0]; dl[1] = *(uint4*)&l[8];

            CP_WAIT0();
            __syncthreads();
            compute(aHi, aLo, bB);
            __syncthreads();
        }
    }

    // ---- epilogue ----
    #pragma unroll
    for (int mi = 0; mi < 2; mi++) {
        #pragma unroll
        for (int half = 0; half < 2; half++) {
            int mrow = wr * 32 + mi * 16 + half * 8 + (lane >> 2);
            int r = rows_s[mrow];
            if (r < 0) continue;
            #pragma unroll
            for (int ni = 0; ni < 8; ni++) {
                int col = n0 + wc * 64 + ni * 8 + ((lane & 3) << 1);
                float v0 = acc[mi][ni][half * 2 + 0] + bias[col];
                float v1 = acc[mi][ni][half * 2 + 1] + bias[col + 1];
                if (GELU) {
                    v0 = 0.5f * v0 * (1.0f + erff(v0 * 0.7071067811865475f));
                    v1 = 0.5f * v1 * (1.0f + erff(v1 * 0.7071067811865475f));
                }
                if (OUT16) {
                    __half hh[2] = {__float2half_rn(v0), __float2half_rn(v1)};
                    *(uint32_t*)(OutH + (size_t)r * N + col) = *(uint32_t*)hh;
                } else {
                    *(float2*)(OutF + (size_t)r * N + col) = make_float2(v0, v1);
                }
            }
        }
    }
}

// ---------------------------------------------------------------------------
// LayerNorm over D=1024; reads fp32 mid, writes fp16 plane.
// ---------------------------------------------------------------------------
__global__ __launch_bounds__(256)
void layernorm_k(const int* __restrict__ ei,
                 const float* __restrict__ ln_g, const float* __restrict__ ln_b,
                 const float* __restrict__ mid,
                 __half* __restrict__ outh)
{
    int r = blockIdx.x;
    int e = ei[r];
    const float* x = mid + (size_t)r * D_;
    int t = threadIdx.x;

    float v[4];
    float s = 0.f, ss = 0.f;
    #pragma unroll
    for (int i = 0; i < 4; i++) {
        v[i] = x[t + i * 256];
        s += v[i];
        ss += v[i] * v[i];
    }
    #pragma unroll
    for (int o = 16; o; o >>= 1) {
        s  += __shfl_xor_sync(0xffffffffu, s,  o);
        ss += __shfl_xor_sync(0xffffffffu, ss, o);
    }
    __shared__ float red[2][8];
    int w = t >> 5, l = t & 31;
    if (l == 0) { red[0][w] = s; red[1][w] = ss; }
    __syncthreads();
    float S = 0.f, SS = 0.f;
    #pragma unroll
    for (int i = 0; i < 8; i++) { S += red[0][i]; SS += red[1][i]; }

    float mu  = S * (1.0f / D_);
    float var = SS * (1.0f / D_) - mu * mu;
    float rstd = rsqrtf(var + LN_EPS);

    const float* gg = ln_g + (size_t)e * D_;
    const float* bb = ln_b + (size_t)e * D_;
    #pragma unroll
    for (int i = 0; i < 4; i++) {
        int c = t + i * 256;
        float y = (v[i] - mu) * rstd * gg[c] + bb[c];
        outh[(size_t)r * D_ + c] = __float2half_rn(y);
    }
}

// ---------------------------------------------------------------------------
extern "C" void kernel_launch(void* const* d_in, const int* in_sizes, int n_in,
                              void* d_out, int out_size)
{
    const float* x   = (const float*)d_in[0];
    const int*   hp  = (const int*)d_in[1];
    const int*   ei  = (const int*)d_in[2];
    const float* pw1 = (const float*)d_in[3];
    const float* pb1 = (const float*)d_in[4];
    const float* pw2 = (const float*)d_in[5];
    const float* pb2 = (const float*)d_in[6];
    const float* qw1 = (const float*)d_in[7];
    const float* qb1 = (const float*)d_in[8];
    const float* qw2 = (const float*)d_in[9];
    const float* qb2 = (const float*)d_in[10];
    const float* lng = (const float*)d_in[11];
    const float* lnb = (const float*)d_in[12];
    const float* tw1 = (const float*)d_in[13];
    const float* tb1 = (const float*)d_in[14];
    const float* tw2 = (const float*)d_in[15];
    const float* tb2 = (const float*)d_in[16];
    float* out = (float*)d_out;

    __half *wh, *h1h, *h2h, *midh;
    float *mid;
    cudaGetSymbolAddress((void**)&wh,   g_wh);
    cudaGetSymbolAddress((void**)&h1h,  g_h1h);
    cudaGetSymbolAddress((void**)&h2h,  g_h2h);
    cudaGetSymbolAddress((void**)&midh, g_midh);
    cudaGetSymbolAddress((void**)&mid,  g_mid);

    static bool attr_done = false;
    if (!attr_done) {
        cudaFuncSetAttribute(gemm_tc<true , false, true >, cudaFuncAttributeMaxDynamicSharedMemorySize, SMEM_BYTES);
        cudaFuncSetAttribute(gemm_tc<false, true , false>, cudaFuncAttributeMaxDynamicSharedMemorySize, SMEM_BYTES);
        cudaFuncSetAttribute(gemm_tc<true , true , true >, cudaFuncAttributeMaxDynamicSharedMemorySize, SMEM_BYTES);
        attr_done = true;
    }

    // Group build (block 0) + pw1/qw1 fp16 conversion (512 extra blocks)
    build_groups_cvt<<<1 + 512, 256>>>(hp, ei, pw1, wh + WH_PW1, qw1, wh + WH_QW1);

    // Stage 1: h1(fp16) = gelu(x @ {p,q}w1 + b1)   K=64, fp32 A, 2-term exact.
    // Extra 64 grid rows convert pw2/qw2 for stage 2.
    gemm_tc<true , false, true ><<<dim3(H_ / TN, MTILES + 64), 256, SMEM_BYTES>>>(
        x, (const __half*)0, S_, H_,
        wh + WH_PW1, wh + WH_QW1, pb1, qb1,
        (float*)0, h1h,
        pw2, wh + WH_PW2, qw2, wh + WH_QW2);
    // Stage 2: mid = h1 @ {p,q}w2 + b2             K=2048, 4-stage pipeline.
    // Extra 128 grid rows convert tw1/tw2 for stages 4/5.
    gemm_tc<false, true , false><<<dim3(D_ / TN, MTILES + 128), 256, SMEM_BYTES>>>(
        (const float*)0, h1h, H_, D_,
        wh + WH_PW2, wh + WH_QW2, pb2, qb2,
        mid, (__half*)0,
        tw1, wh + WH_TW1, tw2, wh + WH_TW2);
    // Stage 3: layernorm -> fp16 plane
    layernorm_k<<<B_, 256>>>(ei, lng, lnb, mid, midh);
    // Stage 4: h2(fp16) = gelu(mid @ tw1 + tb1)    K=1024
    gemm_tc<true , true , true ><<<dim3(H_ / TN, MTILES), 256, SMEM_BYTES>>>(
        (const float*)0, midh, D_, H_,
        wh + WH_TW1, wh + WH_TW1, tb1, tb1,
        (float*)0, h2h,
        (const float*)0, (__half*)0, (const float*)0, (__half*)0);
    // Stage 5: out = h2 @ tw2 + tb2                K=2048
    gemm_tc<false, true , false><<<dim3(D_ / TN, MTILES), 256, SMEM_BYTES>>>(
        (const float*)0, h2h, H_, D_,
        wh + WH_TW2, wh + WH_TW2, tb2, tb2,
        out, (__half*)0,
        (const float*)0, (__half*)0, (const float*)0, (__half*)0);
}